// round 4
// baseline (speedup 1.0000x reference)
#include <cuda_runtime.h>
#include <cuda_bf16.h>
#include <cooperative_groups.h>

namespace cg = cooperative_groups;

// ---------------------------------------------------------------------------
// PointNet++ encoder, B=2, N=16384, 4 SA stages (stride 4, nsample 32)
// ---------------------------------------------------------------------------

// ---------------- scratch buffers (device globals; no allocs allowed) ------
__device__ float g_P[4194304];     // projected feats P  max: 2*64*16384
__device__ float g_h1[16777216];   // layer-1 out        max: 2*64*4096*32
__device__ float g_h2[16777216];   // layer-2 out        max: 2*64*4096*32
__device__ float g_fA[1048576];    // pooled feats ping  max: 2*128*4096
__device__ float g_fB[1048576];    // pooled feats pong
__device__ float g_feats0[98304];  // xyz^T              2*3*16384
__device__ float g_q0[24576];      // query xyz ping     2*4096*3
__device__ float g_q1[24576];      // query xyz pong
__device__ int   g_fpsidx[8192];   // 2*4096
__device__ int   g_ballidx[262144];// 2*4096*32

__device__ __forceinline__ const float* fbufc(int code, const float* ext) {
    switch (code) {
        case 0: return g_P;   case 1: return g_h1;  case 2: return g_h2;
        case 3: return g_fA;  case 4: return g_fB;  case 5: return g_feats0;
        case 6: return g_q0;  case 7: return g_q1;  default: return ext;
    }
}
__device__ __forceinline__ float* fbufw(int code, float* ext) {
    switch (code) {
        case 0: return g_P;   case 1: return g_h1;  case 2: return g_h2;
        case 3: return g_fA;  case 4: return g_fB;  case 5: return g_feats0;
        case 6: return g_q0;  case 7: return g_q1;  default: return ext;
    }
}

// d2 exactly as JAX computes it: ((dx*dx + dy*dy) + dz*dz), no FMA contraction
__device__ __forceinline__ float d2_exact(float dx, float dy, float dz) {
    return __fadd_rn(__fadd_rn(__fmul_rn(dx, dx), __fmul_rn(dy, dy)),
                     __fmul_rn(dz, dz));
}

// ---------------- feats0 = xyz^T  [B,3,N] -----------------------------------
__global__ void k_transpose(const float* __restrict__ xyz) {
    int i = blockIdx.x * blockDim.x + threadIdx.x;
    if (i >= 2 * 16384) return;
    int b = i >> 14, n = i & 16383;
#pragma unroll
    for (int c = 0; c < 3; ++c)
        g_feats0[(b * 3 + c) * 16384 + n] = xyz[(size_t)i * 3 + c];
}

// ---------------- furthest point sampling: 8-CTA cluster per batch ----------
// Push-based cross-CTA exchange: each CTA writes its best (key + coords) into
// ALL 8 CTAs' slot arrays (fire-and-forget DSMEM stores), then does a remote
// release-arrive on each CTA's mbarrier. Waiters acquire-try_wait locally and
// reduce the 8 LOCAL slots (no remote reads, no extra bar on the hot path).
// Slots are parity double-buffered; the arrive(it+1)-after-read(it) program
// order makes parity reuse race-free. Winner coords are carried in-register,
// and the query xyz is written directly (k_query eliminated).
// Tie-break: smallest index via key = (md_bits<<32) | ~idx (jnp.argmax).
__global__ __cluster_dims__(8, 1, 1) __launch_bounds__(512, 1)
void k_fps_cl(const float* __restrict__ ext, int scode, int qcode,
              int N, int npoint) {
    cg::cluster_group cluster = cg::this_cluster();
    const int rank = cluster.block_rank();
    const int b = blockIdx.x >> 3;
    const int tid = threadIdx.x;
    const int Npc = N >> 3;                 // points per CTA
    const int gbase = rank * Npc;

    __shared__ unsigned long long s_wkey[16];
    __shared__ float s_wx[16], s_wy[16], s_wz[16];
    // cluster-exchange slots: [parity][src rank]
    __shared__ unsigned long long s_key[2][8];
    __shared__ float s_x[2][8], s_y[2][8], s_z[2][8];
    __shared__ __align__(8) unsigned long long s_mbar;

    const float* base = fbufc(scode, ext) + (size_t)b * N * 3;

    float px[4], py[4], pz[4], md[4];
#pragma unroll
    for (int j = 0; j < 4; ++j) {
        int i = tid + j * 512;
        md[j] = 1e10f;
        if (i < Npc) {
            const float* p = base + (size_t)(gbase + i) * 3;
            px[j] = p[0]; py[j] = p[1]; pz[j] = p[2];
        } else {
            px[j] = 0.f; py[j] = 0.f; pz[j] = 0.f;
        }
    }

    unsigned mbar32 = (unsigned)__cvta_generic_to_shared(&s_mbar);
    if (tid == 0) {
        asm volatile("mbarrier.init.shared.b64 [%0], %1;"
                     :: "r"(mbar32), "r"(8) : "memory");
    }
    cluster.sync();   // all mbarriers initialized before any remote arrive

    float* qb = fbufw(qcode, nullptr) + (size_t)b * npoint * 3;
    float lx = base[0], ly = base[1], lz = base[2];
    if (rank == 0 && tid == 0) {
        g_fpsidx[b * npoint] = 0;
        qb[0] = lx; qb[1] = ly; qb[2] = lz;
    }

    int par = 0, phase = 0;
    for (int it = 1; it < npoint; ++it) {
        unsigned long long best = 0ull;
        float bx = 0.f, by = 0.f, bz = 0.f;
#pragma unroll
        for (int j = 0; j < 4; ++j) {
            int i = tid + j * 512;
            if (i < Npc) {
                float dx = __fsub_rn(px[j], lx);
                float dy = __fsub_rn(py[j], ly);
                float dz = __fsub_rn(pz[j], lz);
                float d = d2_exact(dx, dy, dz);
                float m = fminf(md[j], d);
                md[j] = m;
                unsigned long long key =
                    ((unsigned long long)__float_as_uint(m) << 32) |
                    (unsigned long long)(0xFFFFFFFFu - (unsigned)(gbase + i));
                if (key > best) { best = key; bx = px[j]; by = py[j]; bz = pz[j]; }
            }
        }
        // intra-warp reduce (key + coords payload)
#pragma unroll
        for (int off = 16; off; off >>= 1) {
            unsigned long long ok = __shfl_down_sync(0xffffffffu, best, off);
            float ox = __shfl_down_sync(0xffffffffu, bx, off);
            float oy = __shfl_down_sync(0xffffffffu, by, off);
            float oz = __shfl_down_sync(0xffffffffu, bz, off);
            if (ok > best) { best = ok; bx = ox; by = oy; bz = oz; }
        }
        if ((tid & 31) == 0) {
            int w = tid >> 5;
            s_wkey[w] = best; s_wx[w] = bx; s_wy[w] = by; s_wz[w] = bz;
        }
        __syncthreads();
        // warp 0: reduce 16 warp-bests, broadcast, publish to all 8 CTAs
        if (tid < 32) {
            unsigned long long k2 = (tid < 16) ? s_wkey[tid] : 0ull;
            float x2 = (tid < 16) ? s_wx[tid] : 0.f;
            float y2 = (tid < 16) ? s_wy[tid] : 0.f;
            float z2 = (tid < 16) ? s_wz[tid] : 0.f;
#pragma unroll
            for (int off = 8; off; off >>= 1) {
                unsigned long long ok = __shfl_down_sync(0xffffffffu, k2, off);
                float ox = __shfl_down_sync(0xffffffffu, x2, off);
                float oy = __shfl_down_sync(0xffffffffu, y2, off);
                float oz = __shfl_down_sync(0xffffffffu, z2, off);
                if (ok > k2) { k2 = ok; x2 = ox; y2 = oy; z2 = oz; }
            }
            k2 = __shfl_sync(0xffffffffu, k2, 0);
            x2 = __shfl_sync(0xffffffffu, x2, 0);
            y2 = __shfl_sync(0xffffffffu, y2, 0);
            z2 = __shfl_sync(0xffffffffu, z2, 0);
            if (tid < 8) {
                // write our best into rank 'tid''s slot[par][myrank]
                *(unsigned long long*)cluster.map_shared_rank(
                    (void*)&s_key[par][rank], tid) = k2;
                *(float*)cluster.map_shared_rank((void*)&s_x[par][rank], tid) = x2;
                *(float*)cluster.map_shared_rank((void*)&s_y[par][rank], tid) = y2;
                *(float*)cluster.map_shared_rank((void*)&s_z[par][rank], tid) = z2;
                // release-arrive on rank 'tid''s mbarrier (orders the stores)
                unsigned ra;
                asm volatile("mapa.shared::cluster.u32 %0, %1, %2;"
                             : "=r"(ra) : "r"(mbar32), "r"(tid));
                asm volatile(
                    "mbarrier.arrive.release.cluster.shared::cluster.b64 _, [%0];"
                    :: "r"(ra) : "memory");
            }
        }
        // all threads: acquire-wait for all 8 arrivals of this phase
        {
            unsigned done;
            asm volatile(
                "{\n\t.reg .pred p;\n\t"
                "mbarrier.try_wait.parity.acquire.cluster.shared::cta.b64 p, [%1], %2;\n\t"
                "selp.b32 %0, 1, 0, p;\n\t}"
                : "=r"(done) : "r"(mbar32), "r"(phase) : "memory");
            while (!done) {
                asm volatile(
                    "{\n\t.reg .pred p;\n\t"
                    "mbarrier.try_wait.parity.acquire.cluster.shared::cta.b64 p, [%1], %2;\n\t"
                    "selp.b32 %0, 1, 0, p;\n\t}"
                    : "=r"(done) : "r"(mbar32), "r"(phase) : "memory");
            }
        }
        phase ^= 1;
        // every thread reduces the 8 local slots (keys first, then coords)
        {
            unsigned long long bk = s_key[par][0];
            int bs = 0;
#pragma unroll
            for (int s = 1; s < 8; ++s) {
                unsigned long long k = s_key[par][s];
                if (k > bk) { bk = k; bs = s; }
            }
            lx = s_x[par][bs]; ly = s_y[par][bs]; lz = s_z[par][bs];
            if (rank == 0 && tid == 0) {
                int sel = (int)(0xFFFFFFFFu - (unsigned)(bk & 0xFFFFFFFFull));
                g_fpsidx[b * npoint + it] = sel;
                qb[it * 3 + 0] = lx; qb[it * 3 + 1] = ly; qb[it * 3 + 2] = lz;
            }
        }
        par ^= 1;
    }
    cluster.sync();
}

// ---------------- ball query: warp per query --------------------------------
__global__ void k_ball(const float* __restrict__ ext, int scode, int qcode,
                       int Q, int Ns, float r2) {
    int gw = (blockIdx.x * blockDim.x + threadIdx.x) >> 5;
    int lane = threadIdx.x & 31;
    if (gw >= 2 * Q) return;
    int b = gw / Q;
    const float* qp = fbufc(qcode, nullptr) + (size_t)gw * 3;
    float qx = qp[0], qy = qp[1], qz = qp[2];
    const float* sp = fbufc(scode, ext) + (size_t)b * Ns * 3;
    int* o = g_ballidx + (size_t)gw * 32;

    int cnt = 0, first = 0;
    for (int base = 0; base < Ns; base += 32) {
        int i = base + lane;                       // Ns is always a mult of 32
        float dx = __fsub_rn(qx, sp[i * 3 + 0]);
        float dy = __fsub_rn(qy, sp[i * 3 + 1]);
        float dz = __fsub_rn(qz, sp[i * 3 + 2]);
        bool hit = d2_exact(dx, dy, dz) < r2;
        unsigned m = __ballot_sync(0xffffffffu, hit);
        if (cnt == 0 && m) first = base + __ffs(m) - 1;
        if (hit) {
            int pos = cnt + __popc(m & ((1u << lane) - 1u));
            if (pos < 32) o[pos] = i;
        }
        cnt += __popc(m);
        if (cnt >= 32) break;
    }
    for (int pos = cnt + lane; pos < 32; pos += 32) o[pos] = first;
}

// ---------------- fused layer-1: h1 = relu(P[:,idx] + W_dp . dp) ------------
// One warp per query point; lane = neighbor. P [C1, N] holds W_f@feat + bias.
__global__ __launch_bounds__(256)
void k_l1(const float* __restrict__ ext, int scode, int qcode,
          const float* __restrict__ W, int CIN, int C1, int Q, int N) {
    extern __shared__ float wdp[];                 // [C1*3]
    int tid = threadIdx.x;
    for (int t = tid; t < C1 * 3; t += 256)
        wdp[t] = W[(t / 3) * CIN + (t % 3)];
    __syncthreads();

    int gw = blockIdx.x * 8 + (tid >> 5);
    int lane = tid & 31;
    if (gw >= 2 * Q) return;
    int b = gw / Q, q = gw % Q;
    long long Nn = (long long)Q * 32;

    const float* qp = fbufc(qcode, nullptr) + (size_t)gw * 3;
    float qx = qp[0], qy = qp[1], qz = qp[2];
    int idx = g_ballidx[(size_t)gw * 32 + lane];
    const float* sp = fbufc(scode, ext) + ((size_t)b * N + idx) * 3;
    float dx = __fsub_rn(sp[0], qx);
    float dy = __fsub_rn(sp[1], qy);
    float dz = __fsub_rn(sp[2], qz);

    const float* Pb = g_P + (size_t)b * C1 * N + idx;
    float* o = g_h1 + (size_t)b * C1 * Nn + (size_t)q * 32 + lane;
#pragma unroll 4
    for (int c = 0; c < C1; ++c) {
        float v = Pb[(size_t)c * N];
        v = fmaf(wdp[c * 3 + 0], dx,
            fmaf(wdp[c * 3 + 1], dy,
            fmaf(wdp[c * 3 + 2], dz, v)));
        o[(size_t)c * Nn] = v > 0.f ? v : 0.f;
    }
}

// ---------------- GEMM: Y = act(W @ X + bias), optional fused max-pool ------
// W [M, ldw] row-major (use cols [0,K)), X [K, Nn] per batch. BN=128 cols,
// 256 threads, TN=8 cols/thread.
template <int BM, int BK, int TM, bool POOL, bool RELU>
__global__ __launch_bounds__(256)
void k_gemm(const float* __restrict__ Wt, const float* __restrict__ bias,
            int xcode, int ycode, float* yext, int M, int K, int ldw,
            long long Nn) {
    __shared__ __align__(16) float As[BK][BM];
    __shared__ __align__(16) float Bs[BK][128];
    int b = blockIdx.z;
    const float* X = fbufc(xcode, nullptr) + (size_t)b * K * Nn;
    int tid = threadIdx.x;
    int tm = tid >> 4, tn = tid & 15;
    int rowBase = blockIdx.y * BM;
    long long colBase = (long long)blockIdx.x * 128;

    float acc[TM][8];
#pragma unroll
    for (int i = 0; i < TM; ++i)
#pragma unroll
        for (int j = 0; j < 8; ++j) acc[i][j] = 0.f;

    for (int k0 = 0; k0 < K; k0 += BK) {
#pragma unroll
        for (int t = tid; t < BM * BK; t += 256) {
            int m = t / BK, kk = t % BK;
            As[kk][m] = (k0 + kk < K) ? Wt[(size_t)(rowBase + m) * ldw + k0 + kk] : 0.f;
        }
#pragma unroll
        for (int t = tid; t < BK * 128; t += 256) {
            int kk = t >> 7, nn = t & 127;
            Bs[kk][nn] = (k0 + kk < K) ? X[(size_t)(k0 + kk) * Nn + colBase + nn] : 0.f;
        }
        __syncthreads();
#pragma unroll
        for (int kk = 0; kk < BK; ++kk) {
            float a[TM], bb[8];
#pragma unroll
            for (int v = 0; v < TM / 4; ++v) {
                float4 a4 = *reinterpret_cast<const float4*>(&As[kk][tm * TM + 4 * v]);
                a[4 * v] = a4.x; a[4 * v + 1] = a4.y;
                a[4 * v + 2] = a4.z; a[4 * v + 3] = a4.w;
            }
            float4 b0 = *reinterpret_cast<const float4*>(&Bs[kk][tn * 8]);
            float4 b1 = *reinterpret_cast<const float4*>(&Bs[kk][tn * 8 + 4]);
            bb[0] = b0.x; bb[1] = b0.y; bb[2] = b0.z; bb[3] = b0.w;
            bb[4] = b1.x; bb[5] = b1.y; bb[6] = b1.z; bb[7] = b1.w;
#pragma unroll
            for (int i = 0; i < TM; ++i)
#pragma unroll
                for (int j = 0; j < 8; ++j)
                    acc[i][j] = fmaf(a[i], bb[j], acc[i][j]);
        }
        __syncthreads();
    }

    if (!POOL) {
        float* Y = fbufw(ycode, yext) + (size_t)b * M * Nn;
#pragma unroll
        for (int i = 0; i < TM; ++i) {
            int row = rowBase + tm * TM + i;
            float bv = bias[row];
            float* yr = Y + (size_t)row * Nn + colBase + tn * 8;
#pragma unroll
            for (int j = 0; j < 8; ++j) {
                float v = acc[i][j] + bv;
                yr[j] = RELU ? (v > 0.f ? v : 0.f) : v;
            }
        }
    } else {
        // max over the 32-neighbor groups (relu/bias commute with max)
        long long Q = Nn >> 5;
        float* Y = fbufw(ycode, yext) + (size_t)b * M * Q;
#pragma unroll
        for (int i = 0; i < TM; ++i) {
            float m = acc[i][0];
#pragma unroll
            for (int j = 1; j < 8; ++j) m = fmaxf(m, acc[i][j]);
            m = fmaxf(m, __shfl_xor_sync(0xffffffffu, m, 1));
            m = fmaxf(m, __shfl_xor_sync(0xffffffffu, m, 2));
            if ((tn & 3) == 0) {
                int row = rowBase + tm * TM + i;
                float v = m + bias[row];
                long long q = (colBase >> 5) + (tn >> 2);
                Y[(size_t)row * Q + q] = v > 0.f ? v : 0.f;
            }
        }
    }
}

// ---------------------------------------------------------------------------
extern "C" void kernel_launch(void* const* d_in, const int* in_sizes, int n_in,
                              void* d_out, int out_size) {
    (void)in_sizes; (void)n_in; (void)out_size;
    const float* xyz = (const float*)d_in[0];
    const float* W[4][3]; const float* BV[4][3];
    {
        int p = 1;
        for (int k = 0; k < 4; ++k)
            for (int l = 0; l < 3; ++l) {
                W[k][l]  = (const float*)d_in[p++];
                BV[k][l] = (const float*)d_in[p++];
            }
    }

    k_transpose<<<(2 * 16384 + 255) / 256, 256>>>(xyz);

    static const int   Ns[4]  = {16384, 4096, 1024, 256};
    static const int   CIN[4] = {6, 131, 259, 515};
    static const int   C1[4]  = {64, 128, 256, 512};
    static const int   C2[4]  = {64, 128, 256, 512};
    static const int   C3[4]  = {128, 256, 512, 1024};
    // r*r rounded exactly as JAX does (double product -> float)
    static const float R2[4]  = {(float)(0.1 * 0.1), (float)(0.2 * 0.2),
                                 (float)(0.4 * 0.4), (float)(0.8 * 0.8)};
    static const int supc[4] = {-1, 6, 7, 6};   // support xyz buffer
    static const int qc[4]   = {6, 7, 6, 7};    // query   xyz buffer
    static const int fic[4]  = {5, 3, 4, 3};    // feats-in buffer
    static const int foc[4]  = {3, 4, 3, -1};   // pooled feats-out (last -> d_out)

    auto gemm = [&](const float* Wp, const float* bp, int xc, int yc, float* ye,
                    int M, int K, int ldw, long long Nn, bool pool, bool relu) {
        if (M >= 128) {
            dim3 g((unsigned)(Nn / 128), M / 128, 2);
            if (pool)
                k_gemm<128, 8, 8, true,  true ><<<g, 256>>>(Wp, bp, xc, yc, ye, M, K, ldw, Nn);
            else if (relu)
                k_gemm<128, 8, 8, false, true ><<<g, 256>>>(Wp, bp, xc, yc, ye, M, K, ldw, Nn);
            else
                k_gemm<128, 8, 8, false, false><<<g, 256>>>(Wp, bp, xc, yc, ye, M, K, ldw, Nn);
        } else {
            dim3 g((unsigned)(Nn / 128), M / 64, 2);
            if (pool)
                k_gemm<64, 16, 4, true,  true ><<<g, 256>>>(Wp, bp, xc, yc, ye, M, K, ldw, Nn);
            else if (relu)
                k_gemm<64, 16, 4, false, true ><<<g, 256>>>(Wp, bp, xc, yc, ye, M, K, ldw, Nn);
            else
                k_gemm<64, 16, 4, false, false><<<g, 256>>>(Wp, bp, xc, yc, ye, M, K, ldw, Nn);
        }
    };

    for (int k = 0; k < 4; ++k) {
        int N = Ns[k], Q = N / 4;
        long long Nn = (long long)Q * 32;

        // FPS (writes fps idx + query xyz directly)
        k_fps_cl<<<16, 512>>>(xyz, supc[k], qc[k], N, Q);
        // P = W_feat @ feats + bias  over SUPPORT points  [C1, N] (no relu)
        gemm(W[k][0] + 3, BV[k][0], fic[k], 0, nullptr,
             C1[k], CIN[k] - 3, CIN[k], (long long)N, false, false);
        // ball query (needs query xyz)
        k_ball<<<(2 * Q * 32 + 255) / 256, 256>>>(xyz, supc[k], qc[k], Q, N, R2[k]);
        // fused layer-1 gather: h1 = relu(P[:, idx] + W_dp . dp)
        k_l1<<<2 * Q / 8, 256, (size_t)C1[k] * 3 * 4>>>(
            xyz, supc[k], qc[k], W[k][0], CIN[k], C1[k], Q, N);
        // layers 2, 3 (3rd fuses neighborhood max-pool)
        gemm(W[k][1], BV[k][1], 1, 2, nullptr,
             C2[k], C1[k], C1[k], Nn, false, true);
        gemm(W[k][2], BV[k][2], 2, foc[k], (float*)d_out,
             C3[k], C2[k], C2[k], Nn, true, true);
    }
}

// round 5
// speedup vs baseline: 1.0291x; 1.0291x over previous
#include <cuda_runtime.h>
#include <cuda_bf16.h>
#include <cooperative_groups.h>

namespace cg = cooperative_groups;

// ---------------------------------------------------------------------------
// PointNet++ encoder, B=2, N=16384, 4 SA stages (stride 4, nsample 32)
// ---------------------------------------------------------------------------

// ---------------- scratch buffers (device globals; no allocs allowed) ------
__device__ float g_P[4194304];     // projected feats P  max: 2*64*16384
__device__ float g_h1[16777216];   // layer-1 out        max: 2*64*4096*32
__device__ float g_h2[16777216];   // layer-2 out        max: 2*64*4096*32
__device__ float g_fA[1048576];    // pooled feats ping  max: 2*128*4096
__device__ float g_fB[1048576];    // pooled feats pong
__device__ float g_feats0[98304];  // xyz^T              2*3*16384
__device__ float g_q0[24576];      // query xyz ping     2*4096*3
__device__ float g_q1[24576];      // query xyz pong
__device__ int   g_fpsidx[8192];   // 2*4096
__device__ int   g_ballidx[262144];// 2*4096*32

__device__ __forceinline__ const float* fbufc(int code, const float* ext) {
    switch (code) {
        case 0: return g_P;   case 1: return g_h1;  case 2: return g_h2;
        case 3: return g_fA;  case 4: return g_fB;  case 5: return g_feats0;
        case 6: return g_q0;  case 7: return g_q1;  default: return ext;
    }
}
__device__ __forceinline__ float* fbufw(int code, float* ext) {
    switch (code) {
        case 0: return g_P;   case 1: return g_h1;  case 2: return g_h2;
        case 3: return g_fA;  case 4: return g_fB;  case 5: return g_feats0;
        case 6: return g_q0;  case 7: return g_q1;  default: return ext;
    }
}

// d2 exactly as JAX computes it: ((dx*dx + dy*dy) + dz*dz), no FMA contraction
__device__ __forceinline__ float d2_exact(float dx, float dy, float dz) {
    return __fadd_rn(__fadd_rn(__fmul_rn(dx, dx), __fmul_rn(dy, dy)),
                     __fmul_rn(dz, dz));
}

// ---------------- feats0 = xyz^T  [B,3,N] -----------------------------------
__global__ void k_transpose(const float* __restrict__ xyz) {
    int i = blockIdx.x * blockDim.x + threadIdx.x;
    if (i >= 2 * 16384) return;
    int b = i >> 14, n = i & 16383;
#pragma unroll
    for (int c = 0; c < 3; ++c)
        g_feats0[(b * 3 + c) * 16384 + n] = xyz[(size_t)i * 3 + c];
}

// ---------------- furthest point sampling: 8-CTA cluster per batch ----------
// Hybrid sync scheme: each CTA PUSHES its best (key + coords) into all 8
// CTAs' parity-double-buffered LOCAL slot arrays (fire-and-forget DSMEM
// stores), then a single cluster.sync() per iteration publishes them
// (arrive=release / wait=acquire). After the sync every thread reduces the 8
// LOCAL smem slots -- no remote reads, no mbarrier polling, no extra bar.
// Parity reuse is race-free: slots[par] for iteration it+2 are only written
// after cluster.sync(it+1), which each reader reaches only after it finished
// reading slots[par] for iteration it.
// Winner coords are carried in-register and query xyz is written directly.
// Tie-break: smallest index via key = (md_bits<<32) | ~idx (jnp.argmax).
__global__ __cluster_dims__(8, 1, 1) __launch_bounds__(512, 1)
void k_fps_cl(const float* __restrict__ ext, int scode, int qcode,
              int N, int npoint) {
    cg::cluster_group cluster = cg::this_cluster();
    const int rank = cluster.block_rank();
    const int b = blockIdx.x >> 3;
    const int tid = threadIdx.x;
    const int Npc = N >> 3;                 // points per CTA
    const int gbase = rank * Npc;

    __shared__ unsigned long long s_wkey[16];
    __shared__ float s_wx[16], s_wy[16], s_wz[16];
    // cluster-exchange slots: [parity][src rank] (remote-written, local-read)
    __shared__ unsigned long long s_key[2][8];
    __shared__ float s_x[2][8], s_y[2][8], s_z[2][8];

    const float* base = fbufc(scode, ext) + (size_t)b * N * 3;

    float px[4], py[4], pz[4], md[4];
#pragma unroll
    for (int j = 0; j < 4; ++j) {
        int i = tid + j * 512;
        md[j] = 1e10f;
        if (i < Npc) {
            const float* p = base + (size_t)(gbase + i) * 3;
            px[j] = p[0]; py[j] = p[1]; pz[j] = p[2];
        } else {
            px[j] = 0.f; py[j] = 0.f; pz[j] = 0.f;
        }
    }

    float* qb = fbufw(qcode, nullptr) + (size_t)b * npoint * 3;
    float lx = base[0], ly = base[1], lz = base[2];
    if (rank == 0 && tid == 0) {
        g_fpsidx[b * npoint] = 0;
        qb[0] = lx; qb[1] = ly; qb[2] = lz;
    }
    cluster.sync();   // slots valid / everyone ready before first exchange

    int par = 0;
    for (int it = 1; it < npoint; ++it) {
        unsigned long long best = 0ull;
        float bx = 0.f, by = 0.f, bz = 0.f;
#pragma unroll
        for (int j = 0; j < 4; ++j) {
            int i = tid + j * 512;
            if (i < Npc) {
                float dx = __fsub_rn(px[j], lx);
                float dy = __fsub_rn(py[j], ly);
                float dz = __fsub_rn(pz[j], lz);
                float d = d2_exact(dx, dy, dz);
                float m = fminf(md[j], d);
                md[j] = m;
                unsigned long long key =
                    ((unsigned long long)__float_as_uint(m) << 32) |
                    (unsigned long long)(0xFFFFFFFFu - (unsigned)(gbase + i));
                if (key > best) { best = key; bx = px[j]; by = py[j]; bz = pz[j]; }
            }
        }
        // intra-warp reduce (key + coords payload)
#pragma unroll
        for (int off = 16; off; off >>= 1) {
            unsigned long long ok = __shfl_down_sync(0xffffffffu, best, off);
            float ox = __shfl_down_sync(0xffffffffu, bx, off);
            float oy = __shfl_down_sync(0xffffffffu, by, off);
            float oz = __shfl_down_sync(0xffffffffu, bz, off);
            if (ok > best) { best = ok; bx = ox; by = oy; bz = oz; }
        }
        if ((tid & 31) == 0) {
            int w = tid >> 5;
            s_wkey[w] = best; s_wx[w] = bx; s_wy[w] = by; s_wz[w] = bz;
        }
        __syncthreads();
        // warp 0: reduce 16 warp-bests, broadcast, push to all 8 CTAs' slots
        if (tid < 32) {
            unsigned long long k2 = (tid < 16) ? s_wkey[tid] : 0ull;
            float x2 = (tid < 16) ? s_wx[tid] : 0.f;
            float y2 = (tid < 16) ? s_wy[tid] : 0.f;
            float z2 = (tid < 16) ? s_wz[tid] : 0.f;
#pragma unroll
            for (int off = 8; off; off >>= 1) {
                unsigned long long ok = __shfl_down_sync(0xffffffffu, k2, off);
                float ox = __shfl_down_sync(0xffffffffu, x2, off);
                float oy = __shfl_down_sync(0xffffffffu, y2, off);
                float oz = __shfl_down_sync(0xffffffffu, z2, off);
                if (ok > k2) { k2 = ok; x2 = ox; y2 = oy; z2 = oz; }
            }
            k2 = __shfl_sync(0xffffffffu, k2, 0);
            x2 = __shfl_sync(0xffffffffu, x2, 0);
            y2 = __shfl_sync(0xffffffffu, y2, 0);
            z2 = __shfl_sync(0xffffffffu, z2, 0);
            if (tid < 8) {
                // write our best into rank 'tid''s slot[par][myrank]
                *(unsigned long long*)cluster.map_shared_rank(
                    (void*)&s_key[par][rank], tid) = k2;
                *(float*)cluster.map_shared_rank((void*)&s_x[par][rank], tid) = x2;
                *(float*)cluster.map_shared_rank((void*)&s_y[par][rank], tid) = y2;
                *(float*)cluster.map_shared_rank((void*)&s_z[par][rank], tid) = z2;
            }
        }
        // publish: arrive releases the DSMEM stores, wait acquires them
        cluster.sync();
        // every thread reduces the 8 local slots
        {
            unsigned long long bk = s_key[par][0];
            int bs = 0;
#pragma unroll
            for (int s = 1; s < 8; ++s) {
                unsigned long long k = s_key[par][s];
                if (k > bk) { bk = k; bs = s; }
            }
            lx = s_x[par][bs]; ly = s_y[par][bs]; lz = s_z[par][bs];
            if (rank == 0 && tid == 0) {
                int sel = (int)(0xFFFFFFFFu - (unsigned)(bk & 0xFFFFFFFFull));
                g_fpsidx[b * npoint + it] = sel;
                qb[it * 3 + 0] = lx; qb[it * 3 + 1] = ly; qb[it * 3 + 2] = lz;
            }
        }
        par ^= 1;
    }
    cluster.sync();
}

// ---------------- ball query: warp per query --------------------------------
__global__ void k_ball(const float* __restrict__ ext, int scode, int qcode,
                       int Q, int Ns, float r2) {
    int gw = (blockIdx.x * blockDim.x + threadIdx.x) >> 5;
    int lane = threadIdx.x & 31;
    if (gw >= 2 * Q) return;
    int b = gw / Q;
    const float* qp = fbufc(qcode, nullptr) + (size_t)gw * 3;
    float qx = qp[0], qy = qp[1], qz = qp[2];
    const float* sp = fbufc(scode, ext) + (size_t)b * Ns * 3;
    int* o = g_ballidx + (size_t)gw * 32;

    int cnt = 0, first = 0;
    for (int base = 0; base < Ns; base += 32) {
        int i = base + lane;                       // Ns is always a mult of 32
        float dx = __fsub_rn(qx, sp[i * 3 + 0]);
        float dy = __fsub_rn(qy, sp[i * 3 + 1]);
        float dz = __fsub_rn(qz, sp[i * 3 + 2]);
        bool hit = d2_exact(dx, dy, dz) < r2;
        unsigned m = __ballot_sync(0xffffffffu, hit);
        if (cnt == 0 && m) first = base + __ffs(m) - 1;
        if (hit) {
            int pos = cnt + __popc(m & ((1u << lane) - 1u));
            if (pos < 32) o[pos] = i;
        }
        cnt += __popc(m);
        if (cnt >= 32) break;
    }
    for (int pos = cnt + lane; pos < 32; pos += 32) o[pos] = first;
}

// ---------------- fused layer-1: h1 = relu(P[:,idx] + W_dp . dp) ------------
// One warp per query point; lane = neighbor. P [C1, N] holds W_f@feat + bias.
__global__ __launch_bounds__(256)
void k_l1(const float* __restrict__ ext, int scode, int qcode,
          const float* __restrict__ W, int CIN, int C1, int Q, int N) {
    extern __shared__ float wdp[];                 // [C1*3]
    int tid = threadIdx.x;
    for (int t = tid; t < C1 * 3; t += 256)
        wdp[t] = W[(t / 3) * CIN + (t % 3)];
    __syncthreads();

    int gw = blockIdx.x * 8 + (tid >> 5);
    int lane = tid & 31;
    if (gw >= 2 * Q) return;
    int b = gw / Q, q = gw % Q;
    long long Nn = (long long)Q * 32;

    const float* qp = fbufc(qcode, nullptr) + (size_t)gw * 3;
    float qx = qp[0], qy = qp[1], qz = qp[2];
    int idx = g_ballidx[(size_t)gw * 32 + lane];
    const float* sp = fbufc(scode, ext) + ((size_t)b * N + idx) * 3;
    float dx = __fsub_rn(sp[0], qx);
    float dy = __fsub_rn(sp[1], qy);
    float dz = __fsub_rn(sp[2], qz);

    const float* Pb = g_P + (size_t)b * C1 * N + idx;
    float* o = g_h1 + (size_t)b * C1 * Nn + (size_t)q * 32 + lane;
#pragma unroll 4
    for (int c = 0; c < C1; ++c) {
        float v = Pb[(size_t)c * N];
        v = fmaf(wdp[c * 3 + 0], dx,
            fmaf(wdp[c * 3 + 1], dy,
            fmaf(wdp[c * 3 + 2], dz, v)));
        o[(size_t)c * Nn] = v > 0.f ? v : 0.f;
    }
}

// ---------------- GEMM: Y = act(W @ X + bias), optional fused max-pool ------
// W [M, ldw] row-major (use cols [0,K)), X [K, Nn] per batch. BN=128 cols,
// 256 threads, TN=8 cols/thread.
template <int BM, int BK, int TM, bool POOL, bool RELU>
__global__ __launch_bounds__(256)
void k_gemm(const float* __restrict__ Wt, const float* __restrict__ bias,
            int xcode, int ycode, float* yext, int M, int K, int ldw,
            long long Nn) {
    __shared__ __align__(16) float As[BK][BM];
    __shared__ __align__(16) float Bs[BK][128];
    int b = blockIdx.z;
    const float* X = fbufc(xcode, nullptr) + (size_t)b * K * Nn;
    int tid = threadIdx.x;
    int tm = tid >> 4, tn = tid & 15;
    int rowBase = blockIdx.y * BM;
    long long colBase = (long long)blockIdx.x * 128;

    float acc[TM][8];
#pragma unroll
    for (int i = 0; i < TM; ++i)
#pragma unroll
        for (int j = 0; j < 8; ++j) acc[i][j] = 0.f;

    for (int k0 = 0; k0 < K; k0 += BK) {
#pragma unroll
        for (int t = tid; t < BM * BK; t += 256) {
            int m = t / BK, kk = t % BK;
            As[kk][m] = (k0 + kk < K) ? Wt[(size_t)(rowBase + m) * ldw + k0 + kk] : 0.f;
        }
#pragma unroll
        for (int t = tid; t < BK * 128; t += 256) {
            int kk = t >> 7, nn = t & 127;
            Bs[kk][nn] = (k0 + kk < K) ? X[(size_t)(k0 + kk) * Nn + colBase + nn] : 0.f;
        }
        __syncthreads();
#pragma unroll
        for (int kk = 0; kk < BK; ++kk) {
            float a[TM], bb[8];
#pragma unroll
            for (int v = 0; v < TM / 4; ++v) {
                float4 a4 = *reinterpret_cast<const float4*>(&As[kk][tm * TM + 4 * v]);
                a[4 * v] = a4.x; a[4 * v + 1] = a4.y;
                a[4 * v + 2] = a4.z; a[4 * v + 3] = a4.w;
            }
            float4 b0 = *reinterpret_cast<const float4*>(&Bs[kk][tn * 8]);
            float4 b1 = *reinterpret_cast<const float4*>(&Bs[kk][tn * 8 + 4]);
            bb[0] = b0.x; bb[1] = b0.y; bb[2] = b0.z; bb[3] = b0.w;
            bb[4] = b1.x; bb[5] = b1.y; bb[6] = b1.z; bb[7] = b1.w;
#pragma unroll
            for (int i = 0; i < TM; ++i)
#pragma unroll
                for (int j = 0; j < 8; ++j)
                    acc[i][j] = fmaf(a[i], bb[j], acc[i][j]);
        }
        __syncthreads();
    }

    if (!POOL) {
        float* Y = fbufw(ycode, yext) + (size_t)b * M * Nn;
#pragma unroll
        for (int i = 0; i < TM; ++i) {
            int row = rowBase + tm * TM + i;
            float bv = bias[row];
            float* yr = Y + (size_t)row * Nn + colBase + tn * 8;
#pragma unroll
            for (int j = 0; j < 8; ++j) {
                float v = acc[i][j] + bv;
                yr[j] = RELU ? (v > 0.f ? v : 0.f) : v;
            }
        }
    } else {
        // max over the 32-neighbor groups (relu/bias commute with max)
        long long Q = Nn >> 5;
        float* Y = fbufw(ycode, yext) + (size_t)b * M * Q;
#pragma unroll
        for (int i = 0; i < TM; ++i) {
            float m = acc[i][0];
#pragma unroll
            for (int j = 1; j < 8; ++j) m = fmaxf(m, acc[i][j]);
            m = fmaxf(m, __shfl_xor_sync(0xffffffffu, m, 1));
            m = fmaxf(m, __shfl_xor_sync(0xffffffffu, m, 2));
            if ((tn & 3) == 0) {
                int row = rowBase + tm * TM + i;
                float v = m + bias[row];
                long long q = (colBase >> 5) + (tn >> 2);
                Y[(size_t)row * Q + q] = v > 0.f ? v : 0.f;
            }
        }
    }
}

// ---------------------------------------------------------------------------
extern "C" void kernel_launch(void* const* d_in, const int* in_sizes, int n_in,
                              void* d_out, int out_size) {
    (void)in_sizes; (void)n_in; (void)out_size;
    const float* xyz = (const float*)d_in[0];
    const float* W[4][3]; const float* BV[4][3];
    {
        int p = 1;
        for (int k = 0; k < 4; ++k)
            for (int l = 0; l < 3; ++l) {
                W[k][l]  = (const float*)d_in[p++];
                BV[k][l] = (const float*)d_in[p++];
            }
    }

    k_transpose<<<(2 * 16384 + 255) / 256, 256>>>(xyz);

    static const int   Ns[4]  = {16384, 4096, 1024, 256};
    static const int   CIN[4] = {6, 131, 259, 515};
    static const int   C1[4]  = {64, 128, 256, 512};
    static const int   C2[4]  = {64, 128, 256, 512};
    static const int   C3[4]  = {128, 256, 512, 1024};
    // r*r rounded exactly as JAX does (double product -> float)
    static const float R2[4]  = {(float)(0.1 * 0.1), (float)(0.2 * 0.2),
                                 (float)(0.4 * 0.4), (float)(0.8 * 0.8)};
    static const int supc[4] = {-1, 6, 7, 6};   // support xyz buffer
    static const int qc[4]   = {6, 7, 6, 7};    // query   xyz buffer
    static const int fic[4]  = {5, 3, 4, 3};    // feats-in buffer
    static const int foc[4]  = {3, 4, 3, -1};   // pooled feats-out (last -> d_out)

    auto gemm = [&](const float* Wp, const float* bp, int xc, int yc, float* ye,
                    int M, int K, int ldw, long long Nn, bool pool, bool relu) {
        if (M >= 128) {
            dim3 g((unsigned)(Nn / 128), M / 128, 2);
            if (pool)
                k_gemm<128, 8, 8, true,  true ><<<g, 256>>>(Wp, bp, xc, yc, ye, M, K, ldw, Nn);
            else if (relu)
                k_gemm<128, 8, 8, false, true ><<<g, 256>>>(Wp, bp, xc, yc, ye, M, K, ldw, Nn);
            else
                k_gemm<128, 8, 8, false, false><<<g, 256>>>(Wp, bp, xc, yc, ye, M, K, ldw, Nn);
        } else {
            dim3 g((unsigned)(Nn / 128), M / 64, 2);
            if (pool)
                k_gemm<64, 16, 4, true,  true ><<<g, 256>>>(Wp, bp, xc, yc, ye, M, K, ldw, Nn);
            else if (relu)
                k_gemm<64, 16, 4, false, true ><<<g, 256>>>(Wp, bp, xc, yc, ye, M, K, ldw, Nn);
            else
                k_gemm<64, 16, 4, false, false><<<g, 256>>>(Wp, bp, xc, yc, ye, M, K, ldw, Nn);
        }
    };

    for (int k = 0; k < 4; ++k) {
        int N = Ns[k], Q = N / 4;
        long long Nn = (long long)Q * 32;

        // FPS (writes fps idx + query xyz directly)
        k_fps_cl<<<16, 512>>>(xyz, supc[k], qc[k], N, Q);
        // P = W_feat @ feats + bias  over SUPPORT points  [C1, N] (no relu)
        gemm(W[k][0] + 3, BV[k][0], fic[k], 0, nullptr,
             C1[k], CIN[k] - 3, CIN[k], (long long)N, false, false);
        // ball query (needs query xyz)
        k_ball<<<(2 * Q * 32 + 255) / 256, 256>>>(xyz, supc[k], qc[k], Q, N, R2[k]);
        // fused layer-1 gather: h1 = relu(P[:, idx] + W_dp . dp)
        k_l1<<<2 * Q / 8, 256, (size_t)C1[k] * 3 * 4>>>(
            xyz, supc[k], qc[k], W[k][0], CIN[k], C1[k], Q, N);
        // layers 2, 3 (3rd fuses neighborhood max-pool)
        gemm(W[k][1], BV[k][1], 1, 2, nullptr,
             C2[k], C1[k], C1[k], Nn, false, true);
        gemm(W[k][2], BV[k][2], 2, foc[k], (float*)d_out,
             C3[k], C2[k], C2[k], Nn, true, true);
    }
}

// round 6
// speedup vs baseline: 1.1929x; 1.1592x over previous
#include <cuda_runtime.h>
#include <cuda_bf16.h>
#include <cooperative_groups.h>

namespace cg = cooperative_groups;

// ---------------------------------------------------------------------------
// PointNet++ encoder, B=2, N=16384, 4 SA stages (stride 4, nsample 32)
// ---------------------------------------------------------------------------

// ---------------- scratch buffers (device globals; no allocs allowed) ------
__device__ float g_P[4194304];     // projected feats P  max: 2*64*16384
__device__ float g_h1[16777216];   // layer-1 out        max: 2*64*4096*32
__device__ float g_h2[16777216];   // layer-2 out        max: 2*64*4096*32
__device__ float g_fA[1048576];    // pooled feats ping  max: 2*128*4096
__device__ float g_fB[1048576];    // pooled feats pong
__device__ float g_feats0[98304];  // xyz^T              2*3*16384
__device__ float g_q0[24576];      // query xyz ping     2*4096*3
__device__ float g_q1[24576];      // query xyz pong
__device__ int   g_fpsidx[8192];   // 2*4096
__device__ int   g_ballidx[262144];// 2*4096*32

__device__ __forceinline__ const float* fbufc(int code, const float* ext) {
    switch (code) {
        case 0: return g_P;   case 1: return g_h1;  case 2: return g_h2;
        case 3: return g_fA;  case 4: return g_fB;  case 5: return g_feats0;
        case 6: return g_q0;  case 7: return g_q1;  default: return ext;
    }
}
__device__ __forceinline__ float* fbufw(int code, float* ext) {
    switch (code) {
        case 0: return g_P;   case 1: return g_h1;  case 2: return g_h2;
        case 3: return g_fA;  case 4: return g_fB;  case 5: return g_feats0;
        case 6: return g_q0;  case 7: return g_q1;  default: return ext;
    }
}

// d2 exactly as JAX computes it: ((dx*dx + dy*dy) + dz*dz), no FMA contraction
__device__ __forceinline__ float d2_exact(float dx, float dy, float dz) {
    return __fadd_rn(__fadd_rn(__fmul_rn(dx, dx), __fmul_rn(dy, dy)),
                     __fmul_rn(dz, dz));
}

// ---------------- feats0 = xyz^T  [B,3,N] -----------------------------------
__global__ void k_transpose(const float* __restrict__ xyz) {
    int i = blockIdx.x * blockDim.x + threadIdx.x;
    if (i >= 2 * 16384) return;
    int b = i >> 14, n = i & 16383;
#pragma unroll
    for (int c = 0; c < 3; ++c)
        g_feats0[(b * 3 + c) * 16384 + n] = xyz[(size_t)i * 3 + c];
}

// ---------------- FPS stage 0: 8-CTA cluster per batch (N=16384) ------------
// Push-based exchange with vectorized DSMEM stores (16B + 4B) + cluster.sync.
// Tie-break: smallest index via key = (md_bits<<32) | ~idx (jnp.argmax).
struct __align__(16) SlotA { unsigned long long key; float x, y; };

__global__ __cluster_dims__(8, 1, 1) __launch_bounds__(512, 1)
void k_fps_cl(const float* __restrict__ xyz, int qcode, int N, int npoint) {
    cg::cluster_group cluster = cg::this_cluster();
    const int rank = cluster.block_rank();
    const int b = blockIdx.x >> 3;
    const int tid = threadIdx.x;
    const int Npc = N >> 3;                 // 2048
    const int gbase = rank * Npc;

    __shared__ unsigned long long s_wkey[16];
    __shared__ float s_wx[16], s_wy[16], s_wz[16];
    __shared__ SlotA s_sa[2][8];            // [parity][src rank]
    __shared__ float s_sz[2][8];

    const float* base = xyz + (size_t)b * N * 3;

    float px[4], py[4], pz[4], md[4];
#pragma unroll
    for (int j = 0; j < 4; ++j) {
        int i = tid + j * 512;              // always < Npc (512*4 == 2048)
        const float* p = base + (size_t)(gbase + i) * 3;
        px[j] = p[0]; py[j] = p[1]; pz[j] = p[2];
        md[j] = 1e10f;
    }

    float* qb = fbufw(qcode, nullptr) + (size_t)b * npoint * 3;
    float lx = base[0], ly = base[1], lz = base[2];
    if (rank == 0 && tid == 0) {
        g_fpsidx[b * npoint] = 0;
        qb[0] = lx; qb[1] = ly; qb[2] = lz;
    }
    cluster.sync();

    int par = 0;
    for (int it = 1; it < npoint; ++it) {
        unsigned long long best = 0ull;
        float bx = 0.f, by = 0.f, bz = 0.f;
#pragma unroll
        for (int j = 0; j < 4; ++j) {
            float dx = __fsub_rn(px[j], lx);
            float dy = __fsub_rn(py[j], ly);
            float dz = __fsub_rn(pz[j], lz);
            float d = d2_exact(dx, dy, dz);
            float m = fminf(md[j], d);
            md[j] = m;
            unsigned long long key =
                ((unsigned long long)__float_as_uint(m) << 32) |
                (unsigned long long)(0xFFFFFFFFu - (unsigned)(gbase + tid + j * 512));
            if (key > best) { best = key; bx = px[j]; by = py[j]; bz = pz[j]; }
        }
#pragma unroll
        for (int off = 16; off; off >>= 1) {
            unsigned long long ok = __shfl_down_sync(0xffffffffu, best, off);
            float ox = __shfl_down_sync(0xffffffffu, bx, off);
            float oy = __shfl_down_sync(0xffffffffu, by, off);
            float oz = __shfl_down_sync(0xffffffffu, bz, off);
            if (ok > best) { best = ok; bx = ox; by = oy; bz = oz; }
        }
        if ((tid & 31) == 0) {
            int w = tid >> 5;
            s_wkey[w] = best; s_wx[w] = bx; s_wy[w] = by; s_wz[w] = bz;
        }
        __syncthreads();
        if (tid < 32) {
            unsigned long long k2 = (tid < 16) ? s_wkey[tid] : 0ull;
            float x2 = (tid < 16) ? s_wx[tid] : 0.f;
            float y2 = (tid < 16) ? s_wy[tid] : 0.f;
            float z2 = (tid < 16) ? s_wz[tid] : 0.f;
#pragma unroll
            for (int off = 8; off; off >>= 1) {
                unsigned long long ok = __shfl_down_sync(0xffffffffu, k2, off);
                float ox = __shfl_down_sync(0xffffffffu, x2, off);
                float oy = __shfl_down_sync(0xffffffffu, y2, off);
                float oz = __shfl_down_sync(0xffffffffu, z2, off);
                if (ok > k2) { k2 = ok; x2 = ox; y2 = oy; z2 = oz; }
            }
            k2 = __shfl_sync(0xffffffffu, k2, 0);
            x2 = __shfl_sync(0xffffffffu, x2, 0);
            y2 = __shfl_sync(0xffffffffu, y2, 0);
            z2 = __shfl_sync(0xffffffffu, z2, 0);
            if (tid < 8) {
                uint4 v;
                v.x = (unsigned)(k2 & 0xFFFFFFFFull);
                v.y = (unsigned)(k2 >> 32);
                v.z = __float_as_uint(x2);
                v.w = __float_as_uint(y2);
                *(uint4*)cluster.map_shared_rank((void*)&s_sa[par][rank], tid) = v;
                *(float*)cluster.map_shared_rank((void*)&s_sz[par][rank], tid) = z2;
            }
        }
        cluster.sync();   // arrive releases DSMEM stores; wait acquires them
        {
            unsigned long long bk = s_sa[par][0].key;
            int bs = 0;
#pragma unroll
            for (int s = 1; s < 8; ++s) {
                unsigned long long k = s_sa[par][s].key;
                if (k > bk) { bk = k; bs = s; }
            }
            lx = s_sa[par][bs].x; ly = s_sa[par][bs].y; lz = s_sz[par][bs];
            if (rank == 0 && tid == 0) {
                int sel = (int)(0xFFFFFFFFu - (unsigned)(bk & 0xFFFFFFFFull));
                g_fpsidx[b * npoint + it] = sel;
                qb[it * 3 + 0] = lx; qb[it * 3 + 1] = ly; qb[it * 3 + 2] = lz;
            }
        }
        par ^= 1;
    }
    cluster.sync();
}

// ---------------- FPS stages 1-3: single CTA per batch ----------------------
// N <= 4096: bar.sync (~50cyc) beats cluster.sync (~380). Same math/keys.
template <int P>
__global__ void k_fps_one(const float* __restrict__ ext, int scode, int qcode,
                          int N, int npoint) {
    const int T = blockDim.x;
    __shared__ unsigned long long s_wkey[32];
    __shared__ float s_wx[32], s_wy[32], s_wz[32];
    __shared__ float s_win[3];
    int b = blockIdx.x;
    int tid = threadIdx.x;
    const float* base = fbufc(scode, ext) + (size_t)b * N * 3;

    float px[P], py[P], pz[P], md[P];
#pragma unroll
    for (int j = 0; j < P; ++j) {
        int i = tid + j * T;
        md[j] = 1e10f;
        if (i < N) {
            const float* p = base + (size_t)i * 3;
            px[j] = p[0]; py[j] = p[1]; pz[j] = p[2];
        } else { px[j] = 0.f; py[j] = 0.f; pz[j] = 0.f; }
    }

    float* qb = fbufw(qcode, nullptr) + (size_t)b * npoint * 3;
    float lx = base[0], ly = base[1], lz = base[2];
    if (tid == 0) {
        g_fpsidx[b * npoint] = 0;
        qb[0] = lx; qb[1] = ly; qb[2] = lz;
    }

    int nw = T >> 5;
    for (int it = 1; it < npoint; ++it) {
        unsigned long long best = 0ull;
        float bx = 0.f, by = 0.f, bz = 0.f;
#pragma unroll
        for (int j = 0; j < P; ++j) {
            int i = tid + j * T;
            if (i < N) {
                float dx = __fsub_rn(px[j], lx);
                float dy = __fsub_rn(py[j], ly);
                float dz = __fsub_rn(pz[j], lz);
                float d = d2_exact(dx, dy, dz);
                float m = fminf(md[j], d);
                md[j] = m;
                unsigned long long key =
                    ((unsigned long long)__float_as_uint(m) << 32) |
                    (unsigned long long)(0xFFFFFFFFu - (unsigned)i);
                if (key > best) { best = key; bx = px[j]; by = py[j]; bz = pz[j]; }
            }
        }
#pragma unroll
        for (int off = 16; off; off >>= 1) {
            unsigned long long ok = __shfl_down_sync(0xffffffffu, best, off);
            float ox = __shfl_down_sync(0xffffffffu, bx, off);
            float oy = __shfl_down_sync(0xffffffffu, by, off);
            float oz = __shfl_down_sync(0xffffffffu, bz, off);
            if (ok > best) { best = ok; bx = ox; by = oy; bz = oz; }
        }
        if ((tid & 31) == 0) {
            int w = tid >> 5;
            s_wkey[w] = best; s_wx[w] = bx; s_wy[w] = by; s_wz[w] = bz;
        }
        __syncthreads();
        if (tid < 32) {
            unsigned long long k2 = (tid < nw) ? s_wkey[tid] : 0ull;
            float x2 = (tid < nw) ? s_wx[tid] : 0.f;
            float y2 = (tid < nw) ? s_wy[tid] : 0.f;
            float z2 = (tid < nw) ? s_wz[tid] : 0.f;
#pragma unroll
            for (int off = 16; off; off >>= 1) {
                unsigned long long ok = __shfl_down_sync(0xffffffffu, k2, off);
                float ox = __shfl_down_sync(0xffffffffu, x2, off);
                float oy = __shfl_down_sync(0xffffffffu, y2, off);
                float oz = __shfl_down_sync(0xffffffffu, z2, off);
                if (ok > k2) { k2 = ok; x2 = ox; y2 = oy; z2 = oz; }
            }
            if (tid == 0) {
                s_win[0] = x2; s_win[1] = y2; s_win[2] = z2;
                int sel = (int)(0xFFFFFFFFu - (unsigned)(k2 & 0xFFFFFFFFull));
                g_fpsidx[b * npoint + it] = sel;
                qb[it * 3 + 0] = x2; qb[it * 3 + 1] = y2; qb[it * 3 + 2] = z2;
            }
        }
        __syncthreads();
        lx = s_win[0]; ly = s_win[1]; lz = s_win[2];
    }
}

// ---------------- ball query: warp per query, 128-pt batches ----------------
// 12 loads issued per outer iteration (MLP), then 4 ballot rounds; early-out
// at 128-pt granularity. Semantics identical (first 32 in index order).
__global__ void k_ball(const float* __restrict__ ext, int scode, int qcode,
                       int Q, int Ns, float r2) {
    int gw = (blockIdx.x * blockDim.x + threadIdx.x) >> 5;
    int lane = threadIdx.x & 31;
    if (gw >= 2 * Q) return;
    int b = gw / Q;
    const float* qp = fbufc(qcode, nullptr) + (size_t)gw * 3;
    float qx = qp[0], qy = qp[1], qz = qp[2];
    const float* sp = fbufc(scode, ext) + (size_t)b * Ns * 3;
    int* o = g_ballidx + (size_t)gw * 32;

    int cnt = 0, first = 0;
    for (int base = 0; base < Ns; base += 128) {   // Ns % 128 == 0 always
        float d2v[4];
#pragma unroll
        for (int j = 0; j < 4; ++j) {
            int i = base + j * 32 + lane;
            float dx = __fsub_rn(qx, __ldg(sp + i * 3 + 0));
            float dy = __fsub_rn(qy, __ldg(sp + i * 3 + 1));
            float dz = __fsub_rn(qz, __ldg(sp + i * 3 + 2));
            d2v[j] = d2_exact(dx, dy, dz);
        }
#pragma unroll
        for (int j = 0; j < 4; ++j) {
            bool hit = d2v[j] < r2;
            unsigned m = __ballot_sync(0xffffffffu, hit);
            if (cnt == 0 && m) first = base + j * 32 + __ffs(m) - 1;
            if (hit) {
                int pos = cnt + __popc(m & ((1u << lane) - 1u));
                if (pos < 32) o[pos] = base + j * 32 + lane;
            }
            cnt += __popc(m);
        }
        if (cnt >= 32) break;
    }
    for (int pos = cnt + lane; pos < 32; pos += 32) o[pos] = first;
}

// ---------------- fused layer-1: h1 = relu(P[:,idx] + W_dp . dp) ------------
__global__ __launch_bounds__(256)
void k_l1(const float* __restrict__ ext, int scode, int qcode,
          const float* __restrict__ W, int CIN, int C1, int Q, int N) {
    extern __shared__ float wdp[];                 // [C1*3]
    int tid = threadIdx.x;
    for (int t = tid; t < C1 * 3; t += 256)
        wdp[t] = W[(t / 3) * CIN + (t % 3)];
    __syncthreads();

    int gw = blockIdx.x * 8 + (tid >> 5);
    int lane = tid & 31;
    if (gw >= 2 * Q) return;
    int b = gw / Q, q = gw % Q;
    long long Nn = (long long)Q * 32;

    const float* qp = fbufc(qcode, nullptr) + (size_t)gw * 3;
    float qx = qp[0], qy = qp[1], qz = qp[2];
    int idx = g_ballidx[(size_t)gw * 32 + lane];
    const float* sp = fbufc(scode, ext) + ((size_t)b * N + idx) * 3;
    float dx = __fsub_rn(sp[0], qx);
    float dy = __fsub_rn(sp[1], qy);
    float dz = __fsub_rn(sp[2], qz);

    const float* Pb = g_P + (size_t)b * C1 * N + idx;
    float* o = g_h1 + (size_t)b * C1 * Nn + (size_t)q * 32 + lane;
#pragma unroll 8
    for (int c = 0; c < C1; ++c) {
        float v = __ldg(Pb + (size_t)c * N);
        v = fmaf(wdp[c * 3 + 0], dx,
            fmaf(wdp[c * 3 + 1], dy,
            fmaf(wdp[c * 3 + 2], dz, v)));
        o[(size_t)c * Nn] = v > 0.f ? v : 0.f;
    }
}

// ---------------- GEMM: Y = act(W @ X + bias), optional fused max-pool ------
// W [M, ldw] row-major (cols [0,K)), X [K, Nn]. BN=128, 256 threads, TN=8.
// GUARD=false: K % BK == 0, smem double-buffered, 1 bar/tile, float4 B loads.
template <int BM, int BK, int TM, bool POOL, bool RELU, bool GUARD>
__global__ __launch_bounds__(256)
void k_gemm(const float* __restrict__ Wt, const float* __restrict__ bias,
            int xcode, int ycode, float* yext, int M, int K, int ldw,
            long long Nn) {
    __shared__ __align__(16) float As[2][BK][BM];
    __shared__ __align__(16) float Bs[2][BK][128];
    int b = blockIdx.z;
    const float* X = fbufc(xcode, nullptr) + (size_t)b * K * Nn;
    int tid = threadIdx.x;
    int tm = tid >> 4, tn = tid & 15;
    int rowBase = blockIdx.y * BM;
    long long colBase = (long long)blockIdx.x * 128;

    float acc[TM][8];
#pragma unroll
    for (int i = 0; i < TM; ++i)
#pragma unroll
        for (int j = 0; j < 8; ++j) acc[i][j] = 0.f;

    if (GUARD) {
        // fallback (small/odd K): single-buffer, guarded loads
        for (int k0 = 0; k0 < K; k0 += BK) {
#pragma unroll
            for (int t = tid; t < BM * BK; t += 256) {
                int m = t / BK, kk = t % BK;
                As[0][kk][m] = (k0 + kk < K)
                    ? Wt[(size_t)(rowBase + m) * ldw + k0 + kk] : 0.f;
            }
#pragma unroll
            for (int t = tid; t < BK * 128; t += 256) {
                int kk = t >> 7, nn = t & 127;
                Bs[0][kk][nn] = (k0 + kk < K)
                    ? X[(size_t)(k0 + kk) * Nn + colBase + nn] : 0.f;
            }
            __syncthreads();
#pragma unroll
            for (int kk = 0; kk < BK; ++kk) {
                float a[TM], bb[8];
#pragma unroll
                for (int v = 0; v < TM / 4; ++v) {
                    float4 a4 = *reinterpret_cast<const float4*>(&As[0][kk][tm * TM + 4 * v]);
                    a[4 * v] = a4.x; a[4 * v + 1] = a4.y;
                    a[4 * v + 2] = a4.z; a[4 * v + 3] = a4.w;
                }
                float4 b0 = *reinterpret_cast<const float4*>(&Bs[0][kk][tn * 8]);
                float4 b1 = *reinterpret_cast<const float4*>(&Bs[0][kk][tn * 8 + 4]);
                bb[0] = b0.x; bb[1] = b0.y; bb[2] = b0.z; bb[3] = b0.w;
                bb[4] = b1.x; bb[5] = b1.y; bb[6] = b1.z; bb[7] = b1.w;
#pragma unroll
                for (int i = 0; i < TM; ++i)
#pragma unroll
                    for (int j = 0; j < 8; ++j)
                        acc[i][j] = fmaf(a[i], bb[j], acc[i][j]);
            }
            __syncthreads();
        }
    } else {
        // pipelined: A scalar loads (ldw may be odd), B float4 loads
        constexpr int AKQ = BK / 4;                 // float-quads per A row
        const int a_m = tid / AKQ;                  // BM=128: tid>>1; BM=64: tid>>2
        const int a_k = (tid % AKQ) * 4;
        const int b_k = tid >> 5;
        const int b_c = (tid & 31) * 4;
        constexpr int BQ = BK / 8;                  // B float4s per thread

        const float* Arow = Wt + (size_t)(rowBase + a_m) * ldw + a_k;
        const float* Bcol = X + colBase + b_c;

        float ra[4];
        float4 rb[BQ];
        // prologue: tile 0 -> smem[0]
#pragma unroll
        for (int i = 0; i < 4; ++i) As[0][a_k + i][a_m] = Arow[i];
#pragma unroll
        for (int v = 0; v < BQ; ++v) {
            int kk = b_k + v * 8;
            *(float4*)&Bs[0][kk][b_c] =
                *(const float4*)(Bcol + (size_t)kk * Nn);
        }
        __syncthreads();

        const int ntiles = K / BK;
        for (int t = 0; t < ntiles; ++t) {
            int cur = t & 1;
            if (t + 1 < ntiles) {
                const float* An = Arow + (t + 1) * BK;
#pragma unroll
                for (int i = 0; i < 4; ++i) ra[i] = An[i];
#pragma unroll
                for (int v = 0; v < BQ; ++v) {
                    int kk = b_k + v * 8;
                    rb[v] = *(const float4*)(Bcol + (size_t)((t + 1) * BK + kk) * Nn);
                }
            }
#pragma unroll
            for (int kk = 0; kk < BK; ++kk) {
                float a[TM], bb[8];
#pragma unroll
                for (int v = 0; v < TM / 4; ++v) {
                    float4 a4 = *reinterpret_cast<const float4*>(&As[cur][kk][tm * TM + 4 * v]);
                    a[4 * v] = a4.x; a[4 * v + 1] = a4.y;
                    a[4 * v + 2] = a4.z; a[4 * v + 3] = a4.w;
                }
                float4 b0 = *reinterpret_cast<const float4*>(&Bs[cur][kk][tn * 8]);
                float4 b1 = *reinterpret_cast<const float4*>(&Bs[cur][kk][tn * 8 + 4]);
                bb[0] = b0.x; bb[1] = b0.y; bb[2] = b0.z; bb[3] = b0.w;
                bb[4] = b1.x; bb[5] = b1.y; bb[6] = b1.z; bb[7] = b1.w;
#pragma unroll
                for (int i = 0; i < TM; ++i)
#pragma unroll
                    for (int j = 0; j < 8; ++j)
                        acc[i][j] = fmaf(a[i], bb[j], acc[i][j]);
            }
            if (t + 1 < ntiles) {
                int nxt = cur ^ 1;
#pragma unroll
                for (int i = 0; i < 4; ++i) As[nxt][a_k + i][a_m] = ra[i];
#pragma unroll
                for (int v = 0; v < BQ; ++v)
                    *(float4*)&Bs[nxt][b_k + v * 8][b_c] = rb[v];
            }
            __syncthreads();
        }
    }

    if (!POOL) {
        float* Y = fbufw(ycode, yext) + (size_t)b * M * Nn;
#pragma unroll
        for (int i = 0; i < TM; ++i) {
            int row = rowBase + tm * TM + i;
            float bv = bias[row];
            float* yr = Y + (size_t)row * Nn + colBase + tn * 8;
#pragma unroll
            for (int j = 0; j < 8; ++j) {
                float v = acc[i][j] + bv;
                yr[j] = RELU ? (v > 0.f ? v : 0.f) : v;
            }
        }
    } else {
        long long Q = Nn >> 5;
        float* Y = fbufw(ycode, yext) + (size_t)b * M * Q;
#pragma unroll
        for (int i = 0; i < TM; ++i) {
            float m = acc[i][0];
#pragma unroll
            for (int j = 1; j < 8; ++j) m = fmaxf(m, acc[i][j]);
            m = fmaxf(m, __shfl_xor_sync(0xffffffffu, m, 1));
            m = fmaxf(m, __shfl_xor_sync(0xffffffffu, m, 2));
            if ((tn & 3) == 0) {
                int row = rowBase + tm * TM + i;
                float v = m + bias[row];
                long long q = (colBase >> 5) + (tn >> 2);
                Y[(size_t)row * Q + q] = v > 0.f ? v : 0.f;
            }
        }
    }
}

// ---------------------------------------------------------------------------
extern "C" void kernel_launch(void* const* d_in, const int* in_sizes, int n_in,
                              void* d_out, int out_size) {
    (void)in_sizes; (void)n_in; (void)out_size;
    const float* xyz = (const float*)d_in[0];
    const float* W[4][3]; const float* BV[4][3];
    {
        int p = 1;
        for (int k = 0; k < 4; ++k)
            for (int l = 0; l < 3; ++l) {
                W[k][l]  = (const float*)d_in[p++];
                BV[k][l] = (const float*)d_in[p++];
            }
    }

    k_transpose<<<(2 * 16384 + 255) / 256, 256>>>(xyz);

    static const int   Ns[4]  = {16384, 4096, 1024, 256};
    static const int   CIN[4] = {6, 131, 259, 515};
    static const int   C1[4]  = {64, 128, 256, 512};
    static const int   C2[4]  = {64, 128, 256, 512};
    static const int   C3[4]  = {128, 256, 512, 1024};
    static const float R2[4]  = {(float)(0.1 * 0.1), (float)(0.2 * 0.2),
                                 (float)(0.4 * 0.4), (float)(0.8 * 0.8)};
    static const int supc[4] = {-1, 6, 7, 6};   // support xyz buffer
    static const int qc[4]   = {6, 7, 6, 7};    // query   xyz buffer
    static const int fic[4]  = {5, 3, 4, 3};    // feats-in buffer
    static const int foc[4]  = {3, 4, 3, -1};   // pooled feats-out

    auto gemm = [&](const float* Wp, const float* bp, int xc, int yc, float* ye,
                    int M, int K, int ldw, long long Nn, bool pool, bool relu) {
        if (M >= 128) {
            dim3 g((unsigned)(Nn / 128), M / 128, 2);
            bool guard = (K % 8) != 0;
            if (guard) {
                if (pool) k_gemm<128, 8, 8, true,  true,  true ><<<g, 256>>>(Wp, bp, xc, yc, ye, M, K, ldw, Nn);
                else if (relu) k_gemm<128, 8, 8, false, true,  true ><<<g, 256>>>(Wp, bp, xc, yc, ye, M, K, ldw, Nn);
                else k_gemm<128, 8, 8, false, false, true ><<<g, 256>>>(Wp, bp, xc, yc, ye, M, K, ldw, Nn);
            } else {
                if (pool) k_gemm<128, 8, 8, true,  true,  false><<<g, 256>>>(Wp, bp, xc, yc, ye, M, K, ldw, Nn);
                else if (relu) k_gemm<128, 8, 8, false, true,  false><<<g, 256>>>(Wp, bp, xc, yc, ye, M, K, ldw, Nn);
                else k_gemm<128, 8, 8, false, false, false><<<g, 256>>>(Wp, bp, xc, yc, ye, M, K, ldw, Nn);
            }
        } else {
            dim3 g((unsigned)(Nn / 128), M / 64, 2);
            bool guard = (K % 16) != 0;
            if (guard) {
                if (pool) k_gemm<64, 16, 4, true,  true,  true ><<<g, 256>>>(Wp, bp, xc, yc, ye, M, K, ldw, Nn);
                else if (relu) k_gemm<64, 16, 4, false, true,  true ><<<g, 256>>>(Wp, bp, xc, yc, ye, M, K, ldw, Nn);
                else k_gemm<64, 16, 4, false, false, true ><<<g, 256>>>(Wp, bp, xc, yc, ye, M, K, ldw, Nn);
            } else {
                if (pool) k_gemm<64, 16, 4, true,  true,  false><<<g, 256>>>(Wp, bp, xc, yc, ye, M, K, ldw, Nn);
                else if (relu) k_gemm<64, 16, 4, false, true,  false><<<g, 256>>>(Wp, bp, xc, yc, ye, M, K, ldw, Nn);
                else k_gemm<64, 16, 4, false, false, false><<<g, 256>>>(Wp, bp, xc, yc, ye, M, K, ldw, Nn);
            }
        }
    };

    for (int k = 0; k < 4; ++k) {
        int N = Ns[k], Q = N / 4;
        long long Nn = (long long)Q * 32;

        // FPS (writes fps idx + query xyz directly)
        if (k == 0) {
            k_fps_cl<<<16, 512>>>(xyz, qc[0], N, Q);
        } else if (k == 1) {
            k_fps_one<4><<<2, 1024>>>(xyz, supc[k], qc[k], N, Q);
        } else if (k == 2) {
            k_fps_one<4><<<2, 256>>>(xyz, supc[k], qc[k], N, Q);
        } else {
            k_fps_one<1><<<2, 256>>>(xyz, supc[k], qc[k], N, Q);
        }
        // P = W_feat @ feats + bias over SUPPORT points [C1, N] (no relu)
        gemm(W[k][0] + 3, BV[k][0], fic[k], 0, nullptr,
             C1[k], CIN[k] - 3, CIN[k], (long long)N, false, false);
        // ball query
        k_ball<<<(2 * Q * 32 + 255) / 256, 256>>>(xyz, supc[k], qc[k], Q, N, R2[k]);
        // fused layer-1 gather
        k_l1<<<2 * Q / 8, 256, (size_t)C1[k] * 3 * 4>>>(
            xyz, supc[k], qc[k], W[k][0], CIN[k], C1[k], Q, N);
        // layers 2, 3 (3rd fuses neighborhood max-pool)
        gemm(W[k][1], BV[k][1], 1, 2, nullptr,
             C2[k], C1[k], C1[k], Nn, false, true);
        gemm(W[k][2], BV[k][2], 2, foc[k], (float*)d_out,
             C3[k], C2[k], C2[k], Nn, true, true);
    }
}

// round 7
// speedup vs baseline: 1.2441x; 1.0429x over previous
#include <cuda_runtime.h>
#include <cuda_bf16.h>
#include <cooperative_groups.h>

namespace cg = cooperative_groups;
typedef unsigned long long u64;

// ---------------------------------------------------------------------------
// PointNet++ encoder, B=2, N=16384, 4 SA stages (stride 4, nsample 32)
// ---------------------------------------------------------------------------

// ---------------- scratch buffers (device globals; no allocs allowed) ------
__device__ float g_P[4194304];     // projected feats P  max: 2*64*16384
__device__ float g_h1[16777216];   // layer-1 out        max: 2*64*4096*32
__device__ float g_h2[16777216];   // layer-2 out        max: 2*64*4096*32
__device__ float g_fA[1048576];    // pooled feats ping  max: 2*128*4096
__device__ float g_fB[1048576];    // pooled feats pong
__device__ float g_feats0[98304];  // xyz^T              2*3*16384
__device__ float g_q0[24576];      // stage0 query xyz   2*4096*3
__device__ float g_q1[6144];       // stage1 query xyz   2*1024*3
__device__ float g_q2[1536];       // stage2 query xyz   2*256*3
__device__ float g_q3[384];        // stage3 query xyz   2*64*3

__device__ __forceinline__ const float* fbufc(int code, const float* ext) {
    switch (code) {
        case 0: return g_P;   case 1: return g_h1;  case 2: return g_h2;
        case 3: return g_fA;  case 4: return g_fB;  case 5: return g_feats0;
        case 6: return g_q0;  case 7: return g_q1;  case 8: return g_q2;
        case 9: return g_q3;  default: return ext;
    }
}
__device__ __forceinline__ float* fbufw(int code, float* ext) {
    switch (code) {
        case 0: return g_P;   case 1: return g_h1;  case 2: return g_h2;
        case 3: return g_fA;  case 4: return g_fB;  case 5: return g_feats0;
        case 6: return g_q0;  case 7: return g_q1;  case 8: return g_q2;
        case 9: return g_q3;  default: return ext;
    }
}

// d2 exactly as JAX computes it: ((dx*dx + dy*dy) + dz*dz), no FMA contraction
__device__ __forceinline__ float d2_exact(float dx, float dy, float dz) {
    return __fadd_rn(__fadd_rn(__fmul_rn(dx, dx), __fmul_rn(dy, dy)),
                     __fmul_rn(dz, dz));
}

// key = (md_bits << 32) | ~idx  (md >= 0 always -> bit compare == value compare)
__device__ __forceinline__ u64 fps_key(float m, int idx) {
    return ((u64)__float_as_uint(m) << 32) |
           (u64)(0xFFFFFFFFu - (unsigned)idx);
}

// ---------------- feats0 = xyz^T  [B,3,N] -----------------------------------
__global__ void k_transpose(const float* __restrict__ xyz) {
    int i = blockIdx.x * blockDim.x + threadIdx.x;
    if (i >= 2 * 16384) return;
    int b = i >> 14, n = i & 16383;
#pragma unroll
    for (int c = 0; c < 3; ++c)
        g_feats0[(b * 3 + c) * 16384 + n] = xyz[(size_t)i * 3 + c];
}

// ---------------- FPS stage 0: 8-CTA cluster per batch (N=16384) ------------
// Push + mbarrier: lanes 0-7 of warp0 write the CTA best (key+coords) into all
// 8 CTAs' parity-double-buffered slots and do a remote release-arrive on each
// CTA's mbarrier (8 expected arrivals/phase). ONLY warp0 polls try_wait; all
// other warps park at __syncthreads (no poll storm -- R3's mistake).
struct __align__(16) SlotA { u64 key; float x, y; };

__global__ __cluster_dims__(8, 1, 1) __launch_bounds__(512, 1)
void k_fps_cl(const float* __restrict__ xyz, int qcode, int N, int npoint) {
    cg::cluster_group cluster = cg::this_cluster();
    const int rank = cluster.block_rank();
    const int b = blockIdx.x >> 3;
    const int tid = threadIdx.x;
    const int gbase = rank * (N >> 3);        // 2048 pts per CTA

    __shared__ u64 s_wkey[16];
    __shared__ float s_wx[16], s_wy[16], s_wz[16];
    __shared__ SlotA s_sa[2][8];              // [parity][src rank]
    __shared__ float s_sz[2][8];
    __shared__ __align__(8) u64 s_mbar;

    const float* base = xyz + (size_t)b * N * 3;

    float px[4], py[4], pz[4], md[4];
#pragma unroll
    for (int j = 0; j < 4; ++j) {
        const float* p = base + (size_t)(gbase + tid + j * 512) * 3;
        px[j] = p[0]; py[j] = p[1]; pz[j] = p[2];
        md[j] = 1e10f;
    }

    unsigned mbar32 = (unsigned)__cvta_generic_to_shared(&s_mbar);
    if (tid == 0)
        asm volatile("mbarrier.init.shared.b64 [%0], %1;"
                     :: "r"(mbar32), "r"(8) : "memory");

    float* qb = fbufw(qcode, nullptr) + (size_t)b * npoint * 3;
    float lx = base[0], ly = base[1], lz = base[2];
    if (rank == 0 && tid == 0) { qb[0] = lx; qb[1] = ly; qb[2] = lz; }
    cluster.sync();                            // mbarriers + slots live

    int par = 0;
    unsigned phase = 0;
    for (int it = 1; it < npoint; ++it) {
        // ---- local update + per-thread argmax (scalar compare) ----
        float bm = -1.f, bx = 0.f, by = 0.f, bz = 0.f;
        int bi = 0;
#pragma unroll
        for (int j = 0; j < 4; ++j) {
            float dx = __fsub_rn(px[j], lx);
            float dy = __fsub_rn(py[j], ly);
            float dz = __fsub_rn(pz[j], lz);
            float d = d2_exact(dx, dy, dz);
            float m = fminf(md[j], d);
            md[j] = m;
            bool p = m > bm;                  // strict: earliest wins ties
            bm = fmaxf(bm, m);
            bx = p ? px[j] : bx; by = p ? py[j] : by; bz = p ? pz[j] : bz;
            bi = p ? (gbase + tid + j * 512) : bi;
        }
        u64 ku = fps_key(bm, bi);             // bm >= 0 always here
        // ---- key-only butterfly; unique winner lane writes warp slot ----
        u64 k1 = ku;
#pragma unroll
        for (int off = 16; off; off >>= 1) {
            u64 o = __shfl_xor_sync(0xffffffffu, k1, off);
            if (o > k1) k1 = o;
        }
        if (ku == k1) {
            int w = tid >> 5;
            s_wkey[w] = k1; s_wx[w] = bx; s_wy[w] = by; s_wz[w] = bz;
        }
        __syncthreads();
        // ---- warp0: reduce 16 warp slots, push to all 8 CTAs, wait ----
        if (tid < 32) {
            u64 ko = (tid < 16) ? s_wkey[tid] : 0ull;
            u64 k2 = ko;
#pragma unroll
            for (int off = 16; off; off >>= 1) {
                u64 o = __shfl_xor_sync(0xffffffffu, k2, off);
                if (o > k2) k2 = o;
            }
            unsigned mb = __ballot_sync(0xffffffffu, ko == k2);
            int wl = __ffs(mb) - 1;
            float x2 = __shfl_sync(0xffffffffu, s_wx[tid & 15], wl);
            float y2 = __shfl_sync(0xffffffffu, s_wy[tid & 15], wl);
            float z2 = __shfl_sync(0xffffffffu, s_wz[tid & 15], wl);
            if (tid < 8) {
                uint4 v;
                v.x = (unsigned)(k2 & 0xFFFFFFFFull);
                v.y = (unsigned)(k2 >> 32);
                v.z = __float_as_uint(x2);
                v.w = __float_as_uint(y2);
                *(uint4*)cluster.map_shared_rank((void*)&s_sa[par][rank], tid) = v;
                *(float*)cluster.map_shared_rank((void*)&s_sz[par][rank], tid) = z2;
                unsigned ra;
                asm volatile("mapa.shared::cluster.u32 %0, %1, %2;"
                             : "=r"(ra) : "r"(mbar32), "r"(tid));
                asm volatile(
                    "mbarrier.arrive.release.cluster.shared::cluster.b64 _, [%0];"
                    :: "r"(ra) : "memory");
            }
            unsigned done = 0;
            while (!done) {
                asm volatile(
                    "{\n\t.reg .pred p;\n\t"
                    "mbarrier.try_wait.parity.acquire.cluster.shared::cta.b64 "
                    "p, [%1], %2, 0x989680;\n\t"
                    "selp.b32 %0, 1, 0, p;\n\t}"
                    : "=r"(done) : "r"(mbar32), "r"(phase) : "memory");
            }
        }
        __syncthreads();                       // releases all warps, orders smem
        // ---- all threads reduce the 8 local slots ----
        {
            u64 bk = s_sa[par][0].key;
            int bs = 0;
#pragma unroll
            for (int s = 1; s < 8; ++s) {
                u64 k = s_sa[par][s].key;
                if (k > bk) { bk = k; bs = s; }
            }
            lx = s_sa[par][bs].x; ly = s_sa[par][bs].y; lz = s_sz[par][bs];
            if (rank == 0 && tid == 0) {
                qb[it * 3 + 0] = lx; qb[it * 3 + 1] = ly; qb[it * 3 + 2] = lz;
            }
        }
        par ^= 1;
        phase ^= 1;
    }
    cluster.sync();                            // keep smem alive for stragglers
}

// ---------------- FPS stages 1-3 merged: one CTA per batch ------------------
__device__ void fps_stage(const float* __restrict__ sup, float* __restrict__ qout,
                          int N, int npoint,
                          u64* s_wkey, float* s_wx, float* s_wy, float* s_wz,
                          float* s_win) {
    int tid = threadIdx.x;
    float px[4], py[4], pz[4], md[4];
#pragma unroll
    for (int j = 0; j < 4; ++j) {
        int i = tid + j * 1024;
        md[j] = 1e10f;
        if (i < N) {
            const float* p = sup + (size_t)i * 3;
            px[j] = p[0]; py[j] = p[1]; pz[j] = p[2];
        } else { px[j] = 0.f; py[j] = 0.f; pz[j] = 0.f; }
    }
    float lx = sup[0], ly = sup[1], lz = sup[2];
    if (tid == 0) { qout[0] = lx; qout[1] = ly; qout[2] = lz; }

    for (int it = 1; it < npoint; ++it) {
        float bm = -1.f, bx = 0.f, by = 0.f, bz = 0.f;
        int bi = 0;
#pragma unroll
        for (int j = 0; j < 4; ++j) {
            int i = tid + j * 1024;
            if (i < N) {
                float dx = __fsub_rn(px[j], lx);
                float dy = __fsub_rn(py[j], ly);
                float dz = __fsub_rn(pz[j], lz);
                float d = d2_exact(dx, dy, dz);
                float m = fminf(md[j], d);
                md[j] = m;
                bool p = m > bm;
                bm = fmaxf(bm, m);
                bx = p ? px[j] : bx; by = p ? py[j] : by; bz = p ? pz[j] : bz;
                bi = p ? i : bi;
            }
        }
        // invalid threads get a unique, always-losing key (hi=0, idx > any valid)
        u64 ku = (bm >= 0.f) ? fps_key(bm, bi)
                             : (u64)(0xFFFFFFFFu - (unsigned)(N + tid));
        u64 k1 = ku;
#pragma unroll
        for (int off = 16; off; off >>= 1) {
            u64 o = __shfl_xor_sync(0xffffffffu, k1, off);
            if (o > k1) k1 = o;
        }
        if (ku == k1) {
            int w = tid >> 5;
            s_wkey[w] = k1; s_wx[w] = bx; s_wy[w] = by; s_wz[w] = bz;
        }
        __syncthreads();
        if (tid < 32) {
            u64 ko = s_wkey[tid];
            u64 k2 = ko;
#pragma unroll
            for (int off = 16; off; off >>= 1) {
                u64 o = __shfl_xor_sync(0xffffffffu, k2, off);
                if (o > k2) k2 = o;
            }
            unsigned mb = __ballot_sync(0xffffffffu, ko == k2);
            int wl = __ffs(mb) - 1;
            float x2 = __shfl_sync(0xffffffffu, s_wx[tid], wl);
            float y2 = __shfl_sync(0xffffffffu, s_wy[tid], wl);
            float z2 = __shfl_sync(0xffffffffu, s_wz[tid], wl);
            if (tid == 0) {
                s_win[0] = x2; s_win[1] = y2; s_win[2] = z2;
                qout[it * 3 + 0] = x2; qout[it * 3 + 1] = y2; qout[it * 3 + 2] = z2;
            }
        }
        __syncthreads();
        lx = s_win[0]; ly = s_win[1]; lz = s_win[2];
    }
}

__global__ __launch_bounds__(1024, 1)
void k_fps_rest() {
    __shared__ u64 s_wkey[32];
    __shared__ float s_wx[32], s_wy[32], s_wz[32], s_win[3];
    int b = blockIdx.x;
    fps_stage(g_q0 + (size_t)b * 4096 * 3, g_q1 + (size_t)b * 1024 * 3,
              4096, 1024, s_wkey, s_wx, s_wy, s_wz, s_win);
    __syncthreads();
    fps_stage(g_q1 + (size_t)b * 1024 * 3, g_q2 + (size_t)b * 256 * 3,
              1024, 256, s_wkey, s_wx, s_wy, s_wz, s_win);
    __syncthreads();
    fps_stage(g_q2 + (size_t)b * 256 * 3, g_q3 + (size_t)b * 64 * 3,
              256, 64, s_wkey, s_wx, s_wy, s_wz, s_win);
}

// ---------------- fused ball query + layer-1 --------------------------------
// One warp per query. Ball: first 32 in-radius indices (ascending), padded
// with first hit; kept in smem. Then h1 = relu(P[:,idx] + W_dp . dp).
__global__ __launch_bounds__(256)
void k_ball_l1(const float* __restrict__ ext, int scode, int qcode,
               const float* __restrict__ W, int CIN, int C1, int Q, int N,
               float r2) {
    extern __shared__ float sm[];
    float* wdp = sm;                           // [C1*3]
    int* sidx = (int*)(sm + C1 * 3);           // [8][32]
    int tid = threadIdx.x;
    for (int t = tid; t < C1 * 3; t += 256)
        wdp[t] = W[(t / 3) * CIN + (t % 3)];
    __syncthreads();

    int wi = tid >> 5, lane = tid & 31;
    int gw = blockIdx.x * 8 + wi;
    if (gw >= 2 * Q) return;
    int b = gw / Q, q = gw % Q;
    long long Nn = (long long)Q * 32;

    const float* qp = fbufc(qcode, nullptr) + (size_t)gw * 3;
    float qx = qp[0], qy = qp[1], qz = qp[2];
    const float* sp = fbufc(scode, ext) + (size_t)b * N * 3;
    int* o = sidx + wi * 32;

    int cnt = 0, first = 0;
    for (int base = 0; base < N; base += 128) {    // N % 128 == 0 always
        float d2v[4];
#pragma unroll
        for (int j = 0; j < 4; ++j) {
            int i = base + j * 32 + lane;
            float dx = __fsub_rn(qx, __ldg(sp + i * 3 + 0));
            float dy = __fsub_rn(qy, __ldg(sp + i * 3 + 1));
            float dz = __fsub_rn(qz, __ldg(sp + i * 3 + 2));
            d2v[j] = d2_exact(dx, dy, dz);
        }
#pragma unroll
        for (int j = 0; j < 4; ++j) {
            bool hit = d2v[j] < r2;
            unsigned m = __ballot_sync(0xffffffffu, hit);
            if (cnt == 0 && m) first = base + j * 32 + __ffs(m) - 1;
            if (hit) {
                int pos = cnt + __popc(m & ((1u << lane) - 1u));
                if (pos < 32) o[pos] = base + j * 32 + lane;
            }
            cnt += __popc(m);
        }
        if (cnt >= 32) break;
    }
    for (int pos = cnt + lane; pos < 32; pos += 32) o[pos] = first;
    __syncwarp();

    int idx = o[lane];
    const float* spp = sp + (size_t)idx * 3;
    float dx = __fsub_rn(spp[0], qx);
    float dy = __fsub_rn(spp[1], qy);
    float dz = __fsub_rn(spp[2], qz);

    const float* Pb = g_P + (size_t)b * C1 * N + idx;
    float* oh = g_h1 + (size_t)b * C1 * Nn + (size_t)q * 32 + lane;
#pragma unroll 8
    for (int c = 0; c < C1; ++c) {
        float v = __ldg(Pb + (size_t)c * N);
        v = fmaf(wdp[c * 3 + 0], dx,
            fmaf(wdp[c * 3 + 1], dy,
            fmaf(wdp[c * 3 + 2], dz, v)));
        oh[(size_t)c * Nn] = v > 0.f ? v : 0.f;
    }
}

// ---------------- GEMM: Y = act(W @ X + bias), optional fused max-pool ------
// W [M, ldw] row-major (cols [0,K)), X [K, Nn]. BN=128, 256 threads, TN=8.
// GUARD=false: K % BK == 0, smem double-buffered, 1 bar/tile.
template <int BM, int BK, int TM, bool POOL, bool RELU, bool GUARD>
__global__ __launch_bounds__(256, 2)
void k_gemm(const float* __restrict__ Wt, const float* __restrict__ bias,
            int xcode, int ycode, float* yext, int M, int K, int ldw,
            long long Nn) {
    __shared__ __align__(16) float As[2][BK][BM];
    __shared__ __align__(16) float Bs[2][BK][128];
    int b = blockIdx.z;
    const float* X = fbufc(xcode, nullptr) + (size_t)b * K * Nn;
    int tid = threadIdx.x;
    int tm = tid >> 4, tn = tid & 15;
    int rowBase = blockIdx.y * BM;
    long long colBase = (long long)blockIdx.x * 128;

    float acc[TM][8];
#pragma unroll
    for (int i = 0; i < TM; ++i)
#pragma unroll
        for (int j = 0; j < 8; ++j) acc[i][j] = 0.f;

    if (GUARD) {
        for (int k0 = 0; k0 < K; k0 += BK) {
#pragma unroll
            for (int t = tid; t < BM * BK; t += 256) {
                int m = t / BK, kk = t % BK;
                As[0][kk][m] = (k0 + kk < K)
                    ? Wt[(size_t)(rowBase + m) * ldw + k0 + kk] : 0.f;
            }
#pragma unroll
            for (int t = tid; t < BK * 128; t += 256) {
                int kk = t >> 7, nn = t & 127;
                Bs[0][kk][nn] = (k0 + kk < K)
                    ? X[(size_t)(k0 + kk) * Nn + colBase + nn] : 0.f;
            }
            __syncthreads();
#pragma unroll
            for (int kk = 0; kk < BK; ++kk) {
                float a[TM], bb[8];
#pragma unroll
                for (int v = 0; v < TM / 4; ++v) {
                    float4 a4 = *reinterpret_cast<const float4*>(&As[0][kk][tm * TM + 4 * v]);
                    a[4 * v] = a4.x; a[4 * v + 1] = a4.y;
                    a[4 * v + 2] = a4.z; a[4 * v + 3] = a4.w;
                }
                float4 b0 = *reinterpret_cast<const float4*>(&Bs[0][kk][tn * 8]);
                float4 b1 = *reinterpret_cast<const float4*>(&Bs[0][kk][tn * 8 + 4]);
                bb[0] = b0.x; bb[1] = b0.y; bb[2] = b0.z; bb[3] = b0.w;
                bb[4] = b1.x; bb[5] = b1.y; bb[6] = b1.z; bb[7] = b1.w;
#pragma unroll
                for (int i = 0; i < TM; ++i)
#pragma unroll
                    for (int j = 0; j < 8; ++j)
                        acc[i][j] = fmaf(a[i], bb[j], acc[i][j]);
            }
            __syncthreads();
        }
    } else {
        constexpr int APT = BM * BK / 256;     // A elems per thread
        constexpr int TPR = BK / APT;          // threads per A row
        constexpr int BQ = BK / 8;             // B float4s per thread
        const int a_m = tid / TPR;
        const int a_k = (tid % TPR) * APT;
        const int b_k = tid >> 5;
        const int b_c = (tid & 31) * 4;

        const float* Arow = Wt + (size_t)(rowBase + a_m) * ldw + a_k;
        const float* Bcol = X + colBase + b_c;

        float ra[APT];
        float4 rb[BQ];
#pragma unroll
        for (int i = 0; i < APT; ++i) As[0][a_k + i][a_m] = Arow[i];
#pragma unroll
        for (int v = 0; v < BQ; ++v) {
            int kk = b_k + v * 8;
            *(float4*)&Bs[0][kk][b_c] = *(const float4*)(Bcol + (size_t)kk * Nn);
        }
        __syncthreads();

        const int ntiles = K / BK;
        for (int t = 0; t < ntiles; ++t) {
            int cur = t & 1;
            if (t + 1 < ntiles) {
                const float* An = Arow + (t + 1) * BK;
#pragma unroll
                for (int i = 0; i < APT; ++i) ra[i] = An[i];
#pragma unroll
                for (int v = 0; v < BQ; ++v) {
                    int kk = b_k + v * 8;
                    rb[v] = *(const float4*)(Bcol + (size_t)((t + 1) * BK + kk) * Nn);
                }
            }
#pragma unroll
            for (int kk = 0; kk < BK; ++kk) {
                float a[TM], bb[8];
#pragma unroll
                for (int v = 0; v < TM / 4; ++v) {
                    float4 a4 = *reinterpret_cast<const float4*>(&As[cur][kk][tm * TM + 4 * v]);
                    a[4 * v] = a4.x; a[4 * v + 1] = a4.y;
                    a[4 * v + 2] = a4.z; a[4 * v + 3] = a4.w;
                }
                float4 b0 = *reinterpret_cast<const float4*>(&Bs[cur][kk][tn * 8]);
                float4 b1 = *reinterpret_cast<const float4*>(&Bs[cur][kk][tn * 8 + 4]);
                bb[0] = b0.x; bb[1] = b0.y; bb[2] = b0.z; bb[3] = b0.w;
                bb[4] = b1.x; bb[5] = b1.y; bb[6] = b1.z; bb[7] = b1.w;
#pragma unroll
                for (int i = 0; i < TM; ++i)
#pragma unroll
                    for (int j = 0; j < 8; ++j)
                        acc[i][j] = fmaf(a[i], bb[j], acc[i][j]);
            }
            if (t + 1 < ntiles) {
                int nxt = cur ^ 1;
#pragma unroll
                for (int i = 0; i < APT; ++i) As[nxt][a_k + i][a_m] = ra[i];
#pragma unroll
                for (int v = 0; v < BQ; ++v)
                    *(float4*)&Bs[nxt][b_k + v * 8][b_c] = rb[v];
            }
            __syncthreads();
        }
    }

    if (!POOL) {
        float* Y = fbufw(ycode, yext) + (size_t)b * M * Nn;
#pragma unroll
        for (int i = 0; i < TM; ++i) {
            int row = rowBase + tm * TM + i;
            float bv = bias[row];
            float* yr = Y + (size_t)row * Nn + colBase + tn * 8;
#pragma unroll
            for (int j = 0; j < 8; ++j) {
                float v = acc[i][j] + bv;
                yr[j] = RELU ? (v > 0.f ? v : 0.f) : v;
            }
        }
    } else {
        long long Q = Nn >> 5;
        float* Y = fbufw(ycode, yext) + (size_t)b * M * Q;
#pragma unroll
        for (int i = 0; i < TM; ++i) {
            float m = acc[i][0];
#pragma unroll
            for (int j = 1; j < 8; ++j) m = fmaxf(m, acc[i][j]);
            m = fmaxf(m, __shfl_xor_sync(0xffffffffu, m, 1));
            m = fmaxf(m, __shfl_xor_sync(0xffffffffu, m, 2));
            if ((tn & 3) == 0) {
                int row = rowBase + tm * TM + i;
                float v = m + bias[row];
                long long q = (colBase >> 5) + (tn >> 2);
                Y[(size_t)row * Q + q] = v > 0.f ? v : 0.f;
            }
        }
    }
}

// ---------------------------------------------------------------------------
extern "C" void kernel_launch(void* const* d_in, const int* in_sizes, int n_in,
                              void* d_out, int out_size) {
    (void)in_sizes; (void)n_in; (void)out_size;
    const float* xyz = (const float*)d_in[0];
    const float* W[4][3]; const float* BV[4][3];
    {
        int p = 1;
        for (int k = 0; k < 4; ++k)
            for (int l = 0; l < 3; ++l) {
                W[k][l]  = (const float*)d_in[p++];
                BV[k][l] = (const float*)d_in[p++];
            }
    }

    k_transpose<<<(2 * 16384 + 255) / 256, 256>>>(xyz);

    static const int   Ns[4]  = {16384, 4096, 1024, 256};
    static const int   CIN[4] = {6, 131, 259, 515};
    static const int   C1[4]  = {64, 128, 256, 512};
    static const int   C2[4]  = {64, 128, 256, 512};
    static const int   C3[4]  = {128, 256, 512, 1024};
    static const float R2[4]  = {(float)(0.1 * 0.1), (float)(0.2 * 0.2),
                                 (float)(0.4 * 0.4), (float)(0.8 * 0.8)};
    static const int supc[4] = {-1, 6, 7, 8};   // support xyz buffer
    static const int qc[4]   = {6, 7, 8, 9};    // query   xyz buffer
    static const int fic[4]  = {5, 3, 4, 3};    // feats-in buffer
    static const int foc[4]  = {3, 4, 3, -1};   // pooled feats-out

    auto gemm = [&](const float* Wp, const float* bp, int xc, int yc, float* ye,
                    int M, int K, int ldw, long long Nn, bool pool, bool relu) {
        bool guard = (K % 16) != 0;
        if (M >= 128) {
            dim3 g((unsigned)(Nn / 128), M / 128, 2);
            if (guard) {
                if (pool) k_gemm<128, 16, 8, true,  true,  true ><<<g, 256>>>(Wp, bp, xc, yc, ye, M, K, ldw, Nn);
                else if (relu) k_gemm<128, 16, 8, false, true,  true ><<<g, 256>>>(Wp, bp, xc, yc, ye, M, K, ldw, Nn);
                else k_gemm<128, 16, 8, false, false, true ><<<g, 256>>>(Wp, bp, xc, yc, ye, M, K, ldw, Nn);
            } else {
                if (pool) k_gemm<128, 16, 8, true,  true,  false><<<g, 256>>>(Wp, bp, xc, yc, ye, M, K, ldw, Nn);
                else if (relu) k_gemm<128, 16, 8, false, true,  false><<<g, 256>>>(Wp, bp, xc, yc, ye, M, K, ldw, Nn);
                else k_gemm<128, 16, 8, false, false, false><<<g, 256>>>(Wp, bp, xc, yc, ye, M, K, ldw, Nn);
            }
        } else {
            dim3 g((unsigned)(Nn / 128), M / 64, 2);
            if (guard) {
                if (pool) k_gemm<64, 16, 4, true,  true,  true ><<<g, 256>>>(Wp, bp, xc, yc, ye, M, K, ldw, Nn);
                else if (relu) k_gemm<64, 16, 4, false, true,  true ><<<g, 256>>>(Wp, bp, xc, yc, ye, M, K, ldw, Nn);
                else k_gemm<64, 16, 4, false, false, true ><<<g, 256>>>(Wp, bp, xc, yc, ye, M, K, ldw, Nn);
            } else {
                if (pool) k_gemm<64, 16, 4, true,  true,  false><<<g, 256>>>(Wp, bp, xc, yc, ye, M, K, ldw, Nn);
                else if (relu) k_gemm<64, 16, 4, false, true,  false><<<g, 256>>>(Wp, bp, xc, yc, ye, M, K, ldw, Nn);
                else k_gemm<64, 16, 4, false, false, false><<<g, 256>>>(Wp, bp, xc, yc, ye, M, K, ldw, Nn);
            }
        }
    };

    // All FPS up front (independent of the MLP pipeline; buffers de-aliased)
    k_fps_cl<<<16, 512>>>(xyz, qc[0], 16384, 4096);
    k_fps_rest<<<2, 1024>>>();

    for (int k = 0; k < 4; ++k) {
        int N = Ns[k], Q = N / 4;
        long long Nn = (long long)Q * 32;

        // P = W_feat @ feats + bias over SUPPORT points [C1, N] (no relu)
        gemm(W[k][0] + 3, BV[k][0], fic[k], 0, nullptr,
             C1[k], CIN[k] - 3, CIN[k], (long long)N, false, false);
        // fused ball query + layer-1
        k_ball_l1<<<2 * Q / 8, 256, (size_t)C1[k] * 3 * 4 + 8 * 32 * 4>>>(
            xyz, supc[k], qc[k], W[k][0], CIN[k], C1[k], Q, N, R2[k]);
        // layers 2, 3 (3rd fuses neighborhood max-pool)
        gemm(W[k][1], BV[k][1], 1, 2, nullptr,
             C2[k], C1[k], C1[k], Nn, false, true);
        gemm(W[k][2], BV[k][2], 2, foc[k], (float*)d_out,
             C3[k], C2[k], C2[k], Nn, true, true);
    }
}

// round 8
// speedup vs baseline: 1.5673x; 1.2598x over previous
#include <cuda_runtime.h>
#include <cuda_bf16.h>
#include <cooperative_groups.h>

namespace cg = cooperative_groups;
typedef unsigned long long u64;

// ---------------------------------------------------------------------------
// PointNet++ encoder, B=2, N=16384, 4 SA stages (stride 4, nsample 32)
// ---------------------------------------------------------------------------

// ---------------- scratch buffers (device globals; no allocs allowed) ------
__device__ float g_P[4194304];     // projected feats P  max: 2*64*16384
__device__ float g_h1[16777216];   // layer-1 out        max: 2*64*4096*32
__device__ float g_h2[16777216];   // layer-2 out        max: 2*64*4096*32
__device__ float g_fA[1048576];    // pooled feats ping  max: 2*128*4096
__device__ float g_fB[1048576];    // pooled feats pong
__device__ float g_feats0[98304];  // xyz^T              2*3*16384
__device__ float g_q0[24576];      // stage0 query xyz   2*4096*3
__device__ float g_q1[6144];       // stage1 query xyz   2*1024*3
__device__ float g_q2[1536];       // stage2 query xyz   2*256*3
__device__ float g_q3[384];        // stage3 query xyz   2*64*3

__device__ __forceinline__ const float* fbufc(int code, const float* ext) {
    switch (code) {
        case 0: return g_P;   case 1: return g_h1;  case 2: return g_h2;
        case 3: return g_fA;  case 4: return g_fB;  case 5: return g_feats0;
        case 6: return g_q0;  case 7: return g_q1;  case 8: return g_q2;
        case 9: return g_q3;  default: return ext;
    }
}
__device__ __forceinline__ float* fbufw(int code, float* ext) {
    switch (code) {
        case 0: return g_P;   case 1: return g_h1;  case 2: return g_h2;
        case 3: return g_fA;  case 4: return g_fB;  case 5: return g_feats0;
        case 6: return g_q0;  case 7: return g_q1;  case 8: return g_q2;
        case 9: return g_q3;  default: return ext;
    }
}

// d2 exactly as JAX computes it: ((dx*dx + dy*dy) + dz*dz), no FMA contraction
__device__ __forceinline__ float d2_exact(float dx, float dy, float dz) {
    return __fadd_rn(__fadd_rn(__fmul_rn(dx, dx), __fmul_rn(dy, dy)),
                     __fmul_rn(dz, dz));
}

// ---- packed f32x2 helpers (rn mul/add: per-lane bit-identical to scalar) ---
__device__ __forceinline__ u64 pack2(float lo, float hi) {
    u64 r; asm("mov.b64 %0,{%1,%2};" : "=l"(r) : "f"(lo), "f"(hi)); return r;
}
__device__ __forceinline__ void unpack2(u64 v, float& lo, float& hi) {
    asm("mov.b64 {%0,%1},%2;" : "=f"(lo), "=f"(hi) : "l"(v));
}
__device__ __forceinline__ u64 add2(u64 a, u64 b) {
    u64 r; asm("add.rn.f32x2 %0,%1,%2;" : "=l"(r) : "l"(a), "l"(b)); return r;
}
__device__ __forceinline__ u64 mul2(u64 a, u64 b) {
    u64 r; asm("mul.rn.f32x2 %0,%1,%2;" : "=l"(r) : "l"(a), "l"(b)); return r;
}

// ---------------- feats0 = xyz^T  [B,3,N] -----------------------------------
__global__ void k_transpose(const float* __restrict__ xyz) {
    int i = blockIdx.x * blockDim.x + threadIdx.x;
    if (i >= 2 * 16384) return;
    int b = i >> 14, n = i & 16383;
#pragma unroll
    for (int c = 0; c < 3; ++c)
        g_feats0[(b * 3 + c) * 16384 + n] = xyz[(size_t)i * 3 + c];
}

// ---------------- FPS stage 0: 8-CTA cluster per batch (N=16384) ------------
// Packed-f32x2 distance update; REDUX-based (max md-bits, then max ~idx)
// reductions; push + remote mbarrier release-arrive; only warp0 polls.
struct __align__(16) SlotA { u64 key; float x, y; };

__global__ __cluster_dims__(8, 1, 1) __launch_bounds__(512, 1)
void k_fps_cl(const float* __restrict__ xyz, int qcode, int N, int npoint) {
    cg::cluster_group cluster = cg::this_cluster();
    const int rank = cluster.block_rank();
    const int b = blockIdx.x >> 3;
    const int tid = threadIdx.x;
    const int gbase = rank * (N >> 3);        // 2048 pts per CTA

    __shared__ unsigned s_whi[16], s_wlo[16];
    __shared__ float s_wx[16], s_wy[16], s_wz[16];
    __shared__ SlotA s_sa[2][8];              // [parity][src rank]
    __shared__ float s_sz[2][8];
    __shared__ __align__(8) u64 s_mbar;

    const float* base = xyz + (size_t)b * N * 3;

    // coords packed in pairs: (pt0,pt1) and (pt2,pt3)
    u64 px01, px23, py01, py23, pz01, pz23;
    float md[4];
    {
        float x[4], y[4], z[4];
#pragma unroll
        for (int j = 0; j < 4; ++j) {
            const float* p = base + (size_t)(gbase + tid + j * 512) * 3;
            x[j] = p[0]; y[j] = p[1]; z[j] = p[2];
            md[j] = 1e10f;
        }
        px01 = pack2(x[0], x[1]); px23 = pack2(x[2], x[3]);
        py01 = pack2(y[0], y[1]); py23 = pack2(y[2], y[3]);
        pz01 = pack2(z[0], z[1]); pz23 = pack2(z[2], z[3]);
    }

    unsigned mbar32 = (unsigned)__cvta_generic_to_shared(&s_mbar);
    if (tid == 0)
        asm volatile("mbarrier.init.shared.b64 [%0], %1;"
                     :: "r"(mbar32), "r"(8) : "memory");

    float* qb = fbufw(qcode, nullptr) + (size_t)b * npoint * 3;
    float lx = base[0], ly = base[1], lz = base[2];
    if (rank == 0 && tid == 0) { qb[0] = lx; qb[1] = ly; qb[2] = lz; }
    cluster.sync();                            // mbarriers + slots live

    int par = 0;
    unsigned phase = 0;
    for (int it = 1; it < npoint; ++it) {
        // ---- packed distance update (sub == add of exact negation) ----
        u64 nlx2 = pack2(-lx, -lx), nly2 = pack2(-ly, -ly), nlz2 = pack2(-lz, -lz);
        float d0, d1, d2, d3;
        {
            u64 dx = add2(px01, nlx2), dy = add2(py01, nly2), dz = add2(pz01, nlz2);
            u64 s = add2(add2(mul2(dx, dx), mul2(dy, dy)), mul2(dz, dz));
            unpack2(s, d0, d1);
        }
        {
            u64 dx = add2(px23, nlx2), dy = add2(py23, nly2), dz = add2(pz23, nlz2);
            u64 s = add2(add2(mul2(dx, dx), mul2(dy, dy)), mul2(dz, dz));
            unpack2(s, d2, d3);
        }
        float m, bm; int bj;
        m = fminf(md[0], d0); md[0] = m; bm = m; bj = 0;
        m = fminf(md[1], d1); md[1] = m; if (m > bm) { bm = m; bj = 1; }
        m = fminf(md[2], d2); md[2] = m; if (m > bm) { bm = m; bj = 2; }
        m = fminf(md[3], d3); md[3] = m; if (m > bm) { bm = m; bj = 3; }

        // ---- warp reduce via REDUX: max md-bits, then max ~idx among ties ---
        unsigned hi = __float_as_uint(bm);     // bm >= 0 -> order-preserving
        unsigned lo = 0xFFFFFFFFu - (unsigned)(gbase + tid + bj * 512);
        unsigned m1 = __reduce_max_sync(0xffffffffu, hi);
        unsigned cnd = (hi == m1) ? lo : 0u;
        unsigned m2 = __reduce_max_sync(0xffffffffu, cnd);
        if (hi == m1 && lo == m2) {            // unique (indices unique)
            u64 cx = (bj < 2) ? px01 : px23;
            u64 cy = (bj < 2) ? py01 : py23;
            u64 cz = (bj < 2) ? pz01 : pz23;
            float xl, xh, yl, yh, zl, zh;
            unpack2(cx, xl, xh); unpack2(cy, yl, yh); unpack2(cz, zl, zh);
            int w = tid >> 5;
            s_whi[w] = m1; s_wlo[w] = m2;
            s_wx[w] = (bj & 1) ? xh : xl;
            s_wy[w] = (bj & 1) ? yh : yl;
            s_wz[w] = (bj & 1) ? zh : zl;
        }
        __syncthreads();
        // ---- warp0: reduce 16 slots, push to all 8 CTAs, wait ----
        if (tid < 32) {
            unsigned hi2 = (tid < 16) ? s_whi[tid] : 0u;
            unsigned lo2 = (tid < 16) ? s_wlo[tid] : 0u;
            unsigned M1 = __reduce_max_sync(0xffffffffu, hi2);
            unsigned c2 = (hi2 == M1) ? lo2 : 0u;
            unsigned M2 = __reduce_max_sync(0xffffffffu, c2);
            unsigned mb = __ballot_sync(0xffffffffu,
                                        (tid < 16) && hi2 == M1 && lo2 == M2);
            int wl = __ffs(mb) - 1;
            float x2 = __shfl_sync(0xffffffffu, s_wx[tid & 15], wl);
            float y2 = __shfl_sync(0xffffffffu, s_wy[tid & 15], wl);
            float z2 = __shfl_sync(0xffffffffu, s_wz[tid & 15], wl);
            if (tid < 8) {
                uint4 v; v.x = M2; v.y = M1;
                v.z = __float_as_uint(x2); v.w = __float_as_uint(y2);
                *(uint4*)cluster.map_shared_rank((void*)&s_sa[par][rank], tid) = v;
                *(float*)cluster.map_shared_rank((void*)&s_sz[par][rank], tid) = z2;
                unsigned ra;
                asm volatile("mapa.shared::cluster.u32 %0, %1, %2;"
                             : "=r"(ra) : "r"(mbar32), "r"(tid));
                asm volatile(
                    "mbarrier.arrive.release.cluster.shared::cluster.b64 _, [%0];"
                    :: "r"(ra) : "memory");
            }
            unsigned done = 0;
            while (!done) {
                asm volatile(
                    "{\n\t.reg .pred p;\n\t"
                    "mbarrier.try_wait.parity.acquire.cluster.shared::cta.b64 "
                    "p, [%1], %2, 0x989680;\n\t"
                    "selp.b32 %0, 1, 0, p;\n\t}"
                    : "=r"(done) : "r"(mbar32), "r"(phase) : "memory");
            }
        }
        __syncthreads();                       // releases all warps, orders smem
        // ---- all threads reduce the 8 local slots ----
        {
            u64 bk = s_sa[par][0].key;
            int bs = 0;
#pragma unroll
            for (int s = 1; s < 8; ++s) {
                u64 k = s_sa[par][s].key;
                if (k > bk) { bk = k; bs = s; }
            }
            lx = s_sa[par][bs].x; ly = s_sa[par][bs].y; lz = s_sz[par][bs];
            if (rank == 0 && tid == 0) {
                qb[it * 3 + 0] = lx; qb[it * 3 + 1] = ly; qb[it * 3 + 2] = lz;
            }
        }
        par ^= 1;
        phase ^= 1;
    }
    cluster.sync();                            // keep smem alive for stragglers
}

// ---------------- FPS stages 1-3 merged: one CTA per batch ------------------
__device__ void fps_stage(const float* __restrict__ sup, float* __restrict__ qout,
                          int N, int npoint,
                          unsigned* s_whi, unsigned* s_wlo,
                          float* s_wx, float* s_wy, float* s_wz, float* s_win) {
    int tid = threadIdx.x;
    float px[4], py[4], pz[4], md[4];
#pragma unroll
    for (int j = 0; j < 4; ++j) {
        int i = tid + j * 1024;
        md[j] = 1e10f;
        if (i < N) {
            const float* p = sup + (size_t)i * 3;
            px[j] = p[0]; py[j] = p[1]; pz[j] = p[2];
        } else { px[j] = 0.f; py[j] = 0.f; pz[j] = 0.f; }
    }
    float lx = sup[0], ly = sup[1], lz = sup[2];
    if (tid == 0) { qout[0] = lx; qout[1] = ly; qout[2] = lz; }
    bool valid = tid < N;

    for (int it = 1; it < npoint; ++it) {
        float bm = -1.f, bx = 0.f, by = 0.f, bz = 0.f;
        int bi = 0;
#pragma unroll
        for (int j = 0; j < 4; ++j) {
            int i = tid + j * 1024;
            if (i < N) {
                float dx = __fsub_rn(px[j], lx);
                float dy = __fsub_rn(py[j], ly);
                float dz = __fsub_rn(pz[j], lz);
                float d = d2_exact(dx, dy, dz);
                float m = fminf(md[j], d);
                md[j] = m;
                bool p = m > bm;
                bm = fmaxf(bm, m);
                bx = p ? px[j] : bx; by = p ? py[j] : by; bz = p ? pz[j] : bz;
                bi = p ? i : bi;
            }
        }
        unsigned hi = valid ? __float_as_uint(bm) : 0u;
        unsigned lo = valid ? (0xFFFFFFFFu - (unsigned)bi)
                            : (0xFFFFFFFFu - (unsigned)(N + tid));
        unsigned m1 = __reduce_max_sync(0xffffffffu, hi);
        unsigned cnd = (hi == m1) ? lo : 0u;
        unsigned m2 = __reduce_max_sync(0xffffffffu, cnd);
        if (hi == m1 && lo == m2) {
            int w = tid >> 5;
            s_whi[w] = m1; s_wlo[w] = m2;
            s_wx[w] = bx; s_wy[w] = by; s_wz[w] = bz;
        }
        __syncthreads();
        if (tid < 32) {
            unsigned hi2 = s_whi[tid], lo2 = s_wlo[tid];
            unsigned M1 = __reduce_max_sync(0xffffffffu, hi2);
            unsigned c2 = (hi2 == M1) ? lo2 : 0u;
            unsigned M2 = __reduce_max_sync(0xffffffffu, c2);
            unsigned mb = __ballot_sync(0xffffffffu, hi2 == M1 && lo2 == M2);
            int wl = __ffs(mb) - 1;
            float x2 = __shfl_sync(0xffffffffu, s_wx[tid], wl);
            float y2 = __shfl_sync(0xffffffffu, s_wy[tid], wl);
            float z2 = __shfl_sync(0xffffffffu, s_wz[tid], wl);
            if (tid == 0) {
                s_win[0] = x2; s_win[1] = y2; s_win[2] = z2;
                qout[it * 3 + 0] = x2; qout[it * 3 + 1] = y2; qout[it * 3 + 2] = z2;
            }
        }
        __syncthreads();
        lx = s_win[0]; ly = s_win[1]; lz = s_win[2];
    }
}

__global__ __launch_bounds__(1024, 1)
void k_fps_rest() {
    __shared__ unsigned s_whi[32], s_wlo[32];
    __shared__ float s_wx[32], s_wy[32], s_wz[32], s_win[3];
    int b = blockIdx.x;
    fps_stage(g_q0 + (size_t)b * 4096 * 3, g_q1 + (size_t)b * 1024 * 3,
              4096, 1024, s_whi, s_wlo, s_wx, s_wy, s_wz, s_win);
    __syncthreads();
    fps_stage(g_q1 + (size_t)b * 1024 * 3, g_q2 + (size_t)b * 256 * 3,
              1024, 256, s_whi, s_wlo, s_wx, s_wy, s_wz, s_win);
    __syncthreads();
    fps_stage(g_q2 + (size_t)b * 256 * 3, g_q3 + (size_t)b * 64 * 3,
              256, 64, s_whi, s_wlo, s_wx, s_wy, s_wz, s_win);
}

// ---------------- fused ball query + layer-1 --------------------------------
__global__ __launch_bounds__(256)
void k_ball_l1(const float* __restrict__ ext, int scode, int qcode,
               const float* __restrict__ W, int CIN, int C1, int Q, int N,
               float r2) {
    extern __shared__ float sm[];
    float* wdp = sm;                           // [C1*3]
    int* sidx = (int*)(sm + C1 * 3);           // [8][32]
    int tid = threadIdx.x;
    for (int t = tid; t < C1 * 3; t += 256)
        wdp[t] = W[(t / 3) * CIN + (t % 3)];
    __syncthreads();

    int wi = tid >> 5, lane = tid & 31;
    int gw = blockIdx.x * 8 + wi;
    if (gw >= 2 * Q) return;
    int b = gw / Q, q = gw % Q;
    long long Nn = (long long)Q * 32;

    const float* qp = fbufc(qcode, nullptr) + (size_t)gw * 3;
    float qx = qp[0], qy = qp[1], qz = qp[2];
    const float* sp = fbufc(scode, ext) + (size_t)b * N * 3;
    int* o = sidx + wi * 32;

    int cnt = 0, first = 0;
    for (int base = 0; base < N; base += 128) {    // N % 128 == 0 always
        float d2v[4];
#pragma unroll
        for (int j = 0; j < 4; ++j) {
            int i = base + j * 32 + lane;
            float dx = __fsub_rn(qx, __ldg(sp + i * 3 + 0));
            float dy = __fsub_rn(qy, __ldg(sp + i * 3 + 1));
            float dz = __fsub_rn(qz, __ldg(sp + i * 3 + 2));
            d2v[j] = d2_exact(dx, dy, dz);
        }
#pragma unroll
        for (int j = 0; j < 4; ++j) {
            bool hit = d2v[j] < r2;
            unsigned m = __ballot_sync(0xffffffffu, hit);
            if (cnt == 0 && m) first = base + j * 32 + __ffs(m) - 1;
            if (hit) {
                int pos = cnt + __popc(m & ((1u << lane) - 1u));
                if (pos < 32) o[pos] = base + j * 32 + lane;
            }
            cnt += __popc(m);
        }
        if (cnt >= 32) break;
    }
    for (int pos = cnt + lane; pos < 32; pos += 32) o[pos] = first;
    __syncwarp();

    int idx = o[lane];
    const float* spp = sp + (size_t)idx * 3;
    float dx = __fsub_rn(spp[0], qx);
    float dy = __fsub_rn(spp[1], qy);
    float dz = __fsub_rn(spp[2], qz);

    const float* Pb = g_P + (size_t)b * C1 * N + idx;
    float* oh = g_h1 + (size_t)b * C1 * Nn + (size_t)q * 32 + lane;
#pragma unroll 8
    for (int c = 0; c < C1; ++c) {
        float v = __ldg(Pb + (size_t)c * N);
        v = fmaf(wdp[c * 3 + 0], dx,
            fmaf(wdp[c * 3 + 1], dy,
            fmaf(wdp[c * 3 + 2], dz, v)));
        oh[(size_t)c * Nn] = v > 0.f ? v : 0.f;
    }
}

// ---------------- GEMM: Y = act(W @ X + bias), optional fused max-pool ------
template <int BM, int BK, int TM, bool POOL, bool RELU, bool GUARD>
__global__ __launch_bounds__(256, 2)
void k_gemm(const float* __restrict__ Wt, const float* __restrict__ bias,
            int xcode, int ycode, float* yext, int M, int K, int ldw,
            long long Nn) {
    __shared__ __align__(16) float As[2][BK][BM];
    __shared__ __align__(16) float Bs[2][BK][128];
    int b = blockIdx.z;
    const float* X = fbufc(xcode, nullptr) + (size_t)b * K * Nn;
    int tid = threadIdx.x;
    int tm = tid >> 4, tn = tid & 15;
    int rowBase = blockIdx.y * BM;
    long long colBase = (long long)blockIdx.x * 128;

    float acc[TM][8];
#pragma unroll
    for (int i = 0; i < TM; ++i)
#pragma unroll
        for (int j = 0; j < 8; ++j) acc[i][j] = 0.f;

    if (GUARD) {
        for (int k0 = 0; k0 < K; k0 += BK) {
#pragma unroll
            for (int t = tid; t < BM * BK; t += 256) {
                int m = t / BK, kk = t % BK;
                As[0][kk][m] = (k0 + kk < K)
                    ? Wt[(size_t)(rowBase + m) * ldw + k0 + kk] : 0.f;
            }
#pragma unroll
            for (int t = tid; t < BK * 128; t += 256) {
                int kk = t >> 7, nn = t & 127;
                Bs[0][kk][nn] = (k0 + kk < K)
                    ? X[(size_t)(k0 + kk) * Nn + colBase + nn] : 0.f;
            }
            __syncthreads();
#pragma unroll
            for (int kk = 0; kk < BK; ++kk) {
                float a[TM], bb[8];
#pragma unroll
                for (int v = 0; v < TM / 4; ++v) {
                    float4 a4 = *reinterpret_cast<const float4*>(&As[0][kk][tm * TM + 4 * v]);
                    a[4 * v] = a4.x; a[4 * v + 1] = a4.y;
                    a[4 * v + 2] = a4.z; a[4 * v + 3] = a4.w;
                }
                float4 b0 = *reinterpret_cast<const float4*>(&Bs[0][kk][tn * 8]);
                float4 b1 = *reinterpret_cast<const float4*>(&Bs[0][kk][tn * 8 + 4]);
                bb[0] = b0.x; bb[1] = b0.y; bb[2] = b0.z; bb[3] = b0.w;
                bb[4] = b1.x; bb[5] = b1.y; bb[6] = b1.z; bb[7] = b1.w;
#pragma unroll
                for (int i = 0; i < TM; ++i)
#pragma unroll
                    for (int j = 0; j < 8; ++j)
                        acc[i][j] = fmaf(a[i], bb[j], acc[i][j]);
            }
            __syncthreads();
        }
    } else {
        constexpr int APT = BM * BK / 256;
        constexpr int TPR = BK / APT;
        constexpr int BQ = BK / 8;
        const int a_m = tid / TPR;
        const int a_k = (tid % TPR) * APT;
        const int b_k = tid >> 5;
        const int b_c = (tid & 31) * 4;

        const float* Arow = Wt + (size_t)(rowBase + a_m) * ldw + a_k;
        const float* Bcol = X + colBase + b_c;

        float ra[APT];
        float4 rb[BQ];
#pragma unroll
        for (int i = 0; i < APT; ++i) As[0][a_k + i][a_m] = Arow[i];
#pragma unroll
        for (int v = 0; v < BQ; ++v) {
            int kk = b_k + v * 8;
            *(float4*)&Bs[0][kk][b_c] = *(const float4*)(Bcol + (size_t)kk * Nn);
        }
        __syncthreads();

        const int ntiles = K / BK;
        for (int t = 0; t < ntiles; ++t) {
            int cur = t & 1;
            if (t + 1 < ntiles) {
                const float* An = Arow + (t + 1) * BK;
#pragma unroll
                for (int i = 0; i < APT; ++i) ra[i] = An[i];
#pragma unroll
                for (int v = 0; v < BQ; ++v) {
                    int kk = b_k + v * 8;
                    rb[v] = *(const float4*)(Bcol + (size_t)((t + 1) * BK + kk) * Nn);
                }
            }
#pragma unroll
            for (int kk = 0; kk < BK; ++kk) {
                float a[TM], bb[8];
#pragma unroll
                for (int v = 0; v < TM / 4; ++v) {
                    float4 a4 = *reinterpret_cast<const float4*>(&As[cur][kk][tm * TM + 4 * v]);
                    a[4 * v] = a4.x; a[4 * v + 1] = a4.y;
                    a[4 * v + 2] = a4.z; a[4 * v + 3] = a4.w;
                }
                float4 b0 = *reinterpret_cast<const float4*>(&Bs[cur][kk][tn * 8]);
                float4 b1 = *reinterpret_cast<const float4*>(&Bs[cur][kk][tn * 8 + 4]);
                bb[0] = b0.x; bb[1] = b0.y; bb[2] = b0.z; bb[3] = b0.w;
                bb[4] = b1.x; bb[5] = b1.y; bb[6] = b1.z; bb[7] = b1.w;
#pragma unroll
                for (int i = 0; i < TM; ++i)
#pragma unroll
                    for (int j = 0; j < 8; ++j)
                        acc[i][j] = fmaf(a[i], bb[j], acc[i][j]);
            }
            if (t + 1 < ntiles) {
                int nxt = cur ^ 1;
#pragma unroll
                for (int i = 0; i < APT; ++i) As[nxt][a_k + i][a_m] = ra[i];
#pragma unroll
                for (int v = 0; v < BQ; ++v)
                    *(float4*)&Bs[nxt][b_k + v * 8][b_c] = rb[v];
            }
            __syncthreads();
        }
    }

    if (!POOL) {
        float* Y = fbufw(ycode, yext) + (size_t)b * M * Nn;
#pragma unroll
        for (int i = 0; i < TM; ++i) {
            int row = rowBase + tm * TM + i;
            float bv = bias[row];
            float* yr = Y + (size_t)row * Nn + colBase + tn * 8;
#pragma unroll
            for (int j = 0; j < 8; ++j) {
                float v = acc[i][j] + bv;
                yr[j] = RELU ? (v > 0.f ? v : 0.f) : v;
            }
        }
    } else {
        long long Q = Nn >> 5;
        float* Y = fbufw(ycode, yext) + (size_t)b * M * Q;
#pragma unroll
        for (int i = 0; i < TM; ++i) {
            float m = acc[i][0];
#pragma unroll
            for (int j = 1; j < 8; ++j) m = fmaxf(m, acc[i][j]);
            m = fmaxf(m, __shfl_xor_sync(0xffffffffu, m, 1));
            m = fmaxf(m, __shfl_xor_sync(0xffffffffu, m, 2));
            if ((tn & 3) == 0) {
                int row = rowBase + tm * TM + i;
                float v = m + bias[row];
                long long q = (colBase >> 5) + (tn >> 2);
                Y[(size_t)row * Q + q] = v > 0.f ? v : 0.f;
            }
        }
    }
}

// ---------------- stream/event handles (created at load, before harness) ----
struct HxStreams {
    cudaStream_t s2; cudaEvent_t evT, evA, evP, evB; bool ok;
    HxStreams() {
        ok = cudaStreamCreateWithFlags(&s2, cudaStreamNonBlocking) == cudaSuccess
          && cudaEventCreateWithFlags(&evT, cudaEventDisableTiming) == cudaSuccess
          && cudaEventCreateWithFlags(&evA, cudaEventDisableTiming) == cudaSuccess
          && cudaEventCreateWithFlags(&evP, cudaEventDisableTiming) == cudaSuccess
          && cudaEventCreateWithFlags(&evB, cudaEventDisableTiming) == cudaSuccess;
        if (!ok) s2 = 0;
    }
};
static HxStreams g_hx;

// ---------------------------------------------------------------------------
extern "C" void kernel_launch(void* const* d_in, const int* in_sizes, int n_in,
                              void* d_out, int out_size) {
    (void)in_sizes; (void)n_in; (void)out_size;
    const float* xyz = (const float*)d_in[0];
    const float* W[4][3]; const float* BV[4][3];
    {
        int p = 1;
        for (int k = 0; k < 4; ++k)
            for (int l = 0; l < 3; ++l) {
                W[k][l]  = (const float*)d_in[p++];
                BV[k][l] = (const float*)d_in[p++];
            }
    }

    static const int   Ns[4]  = {16384, 4096, 1024, 256};
    static const int   CIN[4] = {6, 131, 259, 515};
    static const int   C1[4]  = {64, 128, 256, 512};
    static const int   C2[4]  = {64, 128, 256, 512};
    static const int   C3[4]  = {128, 256, 512, 1024};
    static const float R2[4]  = {(float)(0.1 * 0.1), (float)(0.2 * 0.2),
                                 (float)(0.4 * 0.4), (float)(0.8 * 0.8)};
    static const int supc[4] = {-1, 6, 7, 8};   // support xyz buffer
    static const int qc[4]   = {6, 7, 8, 9};    // query   xyz buffer
    static const int fic[4]  = {5, 3, 4, 3};    // feats-in buffer
    static const int foc[4]  = {3, 4, 3, -1};   // pooled feats-out

    auto gemm = [&](cudaStream_t st, const float* Wp, const float* bp,
                    int xc, int yc, float* ye,
                    int M, int K, int ldw, long long Nn, bool pool, bool relu) {
        bool guard = (K % 16) != 0;
        if (M >= 128) {
            dim3 g((unsigned)(Nn / 128), M / 128, 2);
            if (guard) {
                if (pool) k_gemm<128, 16, 8, true,  true,  true ><<<g, 256, 0, st>>>(Wp, bp, xc, yc, ye, M, K, ldw, Nn);
                else if (relu) k_gemm<128, 16, 8, false, true,  true ><<<g, 256, 0, st>>>(Wp, bp, xc, yc, ye, M, K, ldw, Nn);
                else k_gemm<128, 16, 8, false, false, true ><<<g, 256, 0, st>>>(Wp, bp, xc, yc, ye, M, K, ldw, Nn);
            } else {
                if (pool) k_gemm<128, 16, 8, true,  true,  false><<<g, 256, 0, st>>>(Wp, bp, xc, yc, ye, M, K, ldw, Nn);
                else if (relu) k_gemm<128, 16, 8, false, true,  false><<<g, 256, 0, st>>>(Wp, bp, xc, yc, ye, M, K, ldw, Nn);
                else k_gemm<128, 16, 8, false, false, false><<<g, 256, 0, st>>>(Wp, bp, xc, yc, ye, M, K, ldw, Nn);
            }
        } else {
            dim3 g((unsigned)(Nn / 128), M / 64, 2);
            if (guard) {
                if (pool) k_gemm<64, 16, 4, true,  true,  true ><<<g, 256, 0, st>>>(Wp, bp, xc, yc, ye, M, K, ldw, Nn);
                else if (relu) k_gemm<64, 16, 4, false, true,  true ><<<g, 256, 0, st>>>(Wp, bp, xc, yc, ye, M, K, ldw, Nn);
                else k_gemm<64, 16, 4, false, false, true ><<<g, 256, 0, st>>>(Wp, bp, xc, yc, ye, M, K, ldw, Nn);
            } else {
                if (pool) k_gemm<64, 16, 4, true,  true,  false><<<g, 256, 0, st>>>(Wp, bp, xc, yc, ye, M, K, ldw, Nn);
                else if (relu) k_gemm<64, 16, 4, false, true,  false><<<g, 256, 0, st>>>(Wp, bp, xc, yc, ye, M, K, ldw, Nn);
                else k_gemm<64, 16, 4, false, false, false><<<g, 256, 0, st>>>(Wp, bp, xc, yc, ye, M, K, ldw, Nn);
            }
        }
    };

    const bool ov = g_hx.ok;
    cudaStream_t s2 = ov ? g_hx.s2 : (cudaStream_t)0;

    k_transpose<<<(2 * 16384 + 255) / 256, 256>>>(xyz);
    if (ov) cudaEventRecord(g_hx.evT, 0);

    k_fps_cl<<<16, 512>>>(xyz, qc[0], 16384, 4096);      // stream 0, ~2 ms

    if (ov) {
        cudaEventRecord(g_hx.evA, 0);
        // side stream: stage-0 P-GEMM (needs only feats0), then fps_rest
        cudaStreamWaitEvent(s2, g_hx.evT, 0);
        gemm(s2, W[0][0] + 3, BV[0][0], fic[0], 0, nullptr,
             C1[0], CIN[0] - 3, CIN[0], 16384LL, false, false);
        cudaEventRecord(g_hx.evP, s2);
        cudaStreamWaitEvent(s2, g_hx.evA, 0);
        k_fps_rest<<<2, 1024, 0, s2>>>();
        cudaEventRecord(g_hx.evB, s2);
        cudaStreamWaitEvent(0, g_hx.evP, 0);             // P0 ready for ball_l1
    } else {
        k_fps_rest<<<2, 1024>>>();
        gemm(0, W[0][0] + 3, BV[0][0], fic[0], 0, nullptr,
             C1[0], CIN[0] - 3, CIN[0], 16384LL, false, false);
    }

    for (int k = 0; k < 4; ++k) {
        int N = Ns[k], Q = N / 4;
        long long Nn = (long long)Q * 32;

        if (k >= 1) {
            // P = W_feat @ feats + bias over SUPPORT points (needs prev stage out)
            gemm(0, W[k][0] + 3, BV[k][0], fic[k], 0, nullptr,
                 C1[k], CIN[k] - 3, CIN[k], (long long)N, false, false);
            if (k == 1 && ov) cudaStreamWaitEvent(0, g_hx.evB, 0);  // q1/q2/q3 ready
        }
        // fused ball query + layer-1
        k_ball_l1<<<2 * Q / 8, 256, (size_t)C1[k] * 3 * 4 + 8 * 32 * 4>>>(
            xyz, supc[k], qc[k], W[k][0], CIN[k], C1[k], Q, N, R2[k]);
        // layers 2, 3 (3rd fuses neighborhood max-pool)
        gemm(0, W[k][1], BV[k][1], 1, 2, nullptr,
             C2[k], C1[k], C1[k], Nn, false, true);
        gemm(0, W[k][2], BV[k][2], 2, foc[k], (float*)d_out,
             C3[k], C2[k], C2[k], Nn, true, true);
    }
}